// round 2
// baseline (speedup 1.0000x reference)
#include <cuda_runtime.h>
#include <cuda_bf16.h>
#include <math.h>

// ---------------------------------------------------------------------------
// SelfReferentialField: two MoE engines + self-referential tension loop.
// Shapes: B=2048, IN=1024, HID=2048, OUT=1024, N_EXP_A=12 (top-4), N_EXP_G=6.
// All fp32. Strategy: route EngineA tokens (top-4 of 12) to cut FLOPs 3x on A,
// classic 128x128x8 shared-memory SGEMM with fused epilogues.
// ---------------------------------------------------------------------------

#define BATCH   2048
#define IN_DIM  1024
#define HID_DIM 2048
#define OUT_DIM 1024
#define NEXPA   12
#define TOPKA   4
#define NEXPG   6

// H_TARGET = -(0.5 ln 0.5 + (1/3) ln(1/3) + (1/6) ln(1/6))
#define H_TARGET 1.0114042647073518f

// ------------------------- device scratch (static) -------------------------
__device__ float g_h     [BATCH * HID_DIM];   // per-expert hidden (reused)
__device__ float g_out_p [BATCH * OUT_DIM];   // out_plus
__device__ float g_out_m [BATCH * OUT_DIM];   // out_minus
__device__ float g_rep   [BATCH * OUT_DIM];   // repulsion
__device__ float g_mr    [BATCH * OUT_DIM];   // modified repulsion
__device__ float g_ss    [BATCH * OUT_DIM];   // self_state
__device__ float g_h1    [BATCH * HID_DIM];   // self-model hidden
__device__ float g_wa    [BATCH * NEXPA];     // dense A weights (zeros except top4)
__device__ float g_wg    [BATCH * NEXPG];     // G softmax weights
__device__ float g_ent   [BATCH];             // per-token entropy
__device__ float g_pt    [BATCH];             // prev_tension per row
__device__ float g_tens  [8];                 // tensions[0..3]
__device__ int   g_cnt   [NEXPA];             // routed counts per A expert
__device__ int   g_list  [NEXPA * BATCH];     // routed token ids
__device__ float g_wcomp [NEXPA * BATCH];     // routed weights

// ------------------------------ helpers ------------------------------------
__device__ __forceinline__ float block_reduce_sum(float v) {
    __shared__ float s[32];
    int lane = threadIdx.x & 31, w = threadIdx.x >> 5;
    #pragma unroll
    for (int o = 16; o > 0; o >>= 1) v += __shfl_down_sync(0xffffffffu, v, o);
    if (lane == 0) s[w] = v;
    __syncthreads();
    int nw = blockDim.x >> 5;
    v = (threadIdx.x < nw) ? s[threadIdx.x] : 0.f;
    if (w == 0) {
        #pragma unroll
        for (int o = 16; o > 0; o >>= 1) v += __shfl_down_sync(0xffffffffu, v, o);
    }
    return v;  // valid on thread 0
}

// ------------------------------ zero ----------------------------------------
__global__ void zero_kernel() {
    int i = blockIdx.x * blockDim.x + threadIdx.x;
    if (i < BATCH * OUT_DIM) { g_out_p[i] = 0.f; g_out_m[i] = 0.f; }
}

// ------------------------------ gating --------------------------------------
// One block per token: 18 dot products of length 1024, then top-4 softmax (A),
// dense softmax + entropy (G).
__global__ __launch_bounds__(256) void gate_kernel(
    const float* __restrict__ x,
    const float* __restrict__ gaw, const float* __restrict__ gab,
    const float* __restrict__ ggw, const float* __restrict__ ggb)
{
    int b = blockIdx.x;
    int tid = threadIdx.x;
    float acc[18];
    #pragma unroll
    for (int e = 0; e < 18; e++) acc[e] = 0.f;
    const float* xr = x + (size_t)b * IN_DIM;
    for (int i = tid; i < IN_DIM; i += 256) {
        float xv = xr[i];
        #pragma unroll
        for (int e = 0; e < NEXPA; e++) acc[e] = fmaf(xv, gaw[i * NEXPA + e], acc[e]);
        #pragma unroll
        for (int e = 0; e < NEXPG; e++) acc[12 + e] = fmaf(xv, ggw[i * NEXPG + e], acc[12 + e]);
    }
    __shared__ float s[18][8];
    int lane = tid & 31, w = tid >> 5;
    #pragma unroll
    for (int e = 0; e < 18; e++) {
        float v = acc[e];
        #pragma unroll
        for (int o = 16; o > 0; o >>= 1) v += __shfl_down_sync(0xffffffffu, v, o);
        if (lane == 0) s[e][w] = v;
    }
    __syncthreads();
    if (tid == 0) {
        float logits[18];
        for (int e = 0; e < 18; e++) {
            float v = 0.f;
            for (int ww = 0; ww < 8; ww++) v += s[e][ww];
            logits[e] = v + (e < 12 ? gab[e] : ggb[e - 12]);
        }
        // ---- top-4 of A ----
        bool used[NEXPA];
        for (int e = 0; e < NEXPA; e++) used[e] = false;
        int   idxs[TOPKA];
        float vals[TOPKA];
        for (int k = 0; k < TOPKA; k++) {
            int bi = -1; float bv = -INFINITY;
            for (int e = 0; e < NEXPA; e++)
                if (!used[e] && logits[e] > bv) { bv = logits[e]; bi = e; }
            used[bi] = true; idxs[k] = bi; vals[k] = bv;
        }
        float m = vals[0], sum = 0.f, wv[TOPKA];
        for (int k = 0; k < TOPKA; k++) { wv[k] = expf(vals[k] - m); sum += wv[k]; }
        for (int e = 0; e < NEXPA; e++) g_wa[b * NEXPA + e] = 0.f;
        for (int k = 0; k < TOPKA; k++) g_wa[b * NEXPA + idxs[k]] = wv[k] / sum;
        // ---- G softmax + entropy ----
        float mg = -INFINITY;
        for (int e = 0; e < NEXPG; e++) mg = fmaxf(mg, logits[12 + e]);
        float sg = 0.f, eg[NEXPG];
        for (int e = 0; e < NEXPG; e++) { eg[e] = expf(logits[12 + e] - mg); sg += eg[e]; }
        float ent = 0.f;
        for (int e = 0; e < NEXPG; e++) {
            float wge = eg[e] / sg;
            g_wg[b * NEXPG + e] = wge;
            ent -= wge * logf(wge + 1e-8f);
        }
        g_ent[b] = ent;
    }
}

// ------------------------------ routing -------------------------------------
// 12 warps, warp e compacts tokens with weight>0 deterministically via ballot.
__global__ void route_kernel() {
    int wid = threadIdx.x >> 5, lane = threadIdx.x & 31;
    if (wid >= NEXPA) return;
    int cnt = 0;
    for (int base = 0; base < BATCH; base += 32) {
        int b = base + lane;
        float w = g_wa[b * NEXPA + wid];
        bool sel = (w > 0.f);
        unsigned m = __ballot_sync(0xffffffffu, sel);
        if (sel) {
            int pos = cnt + __popc(m & ((1u << lane) - 1u));
            g_list[wid * BATCH + pos]  = b;
            g_wcomp[wid * BATCH + pos] = w;
        }
        cnt += __popc(m);
    }
    if (lane == 0) g_cnt[wid] = cnt;
}

// ------------------------------ SGEMM ---------------------------------------
// 128x128 tile, BK=8, 256 threads, 8x8 micro-tile.
// MODE 0: C = relu(A@B + bias)                 (store to compact rows)
// MODE 1: C[rowsC[m]] += w[m]*(A@B + bias)     (scatter weighted accumulate)
// MODE 2: C = tanh(A@B + bias)
// MODE 3: C = addend + A@B + bias
// MODE 4: C = 0.5*(ex1+ex2) + tscale*sqrt(pt[m]+1e-8)*tanh(A@B + bias)
#define BM 128
#define BN 128
#define BKD 8

template<int MODE>
__global__ __launch_bounds__(256) void gemm_k(
    const float* __restrict__ A, const float* __restrict__ B,
    const float* __restrict__ bias, float* __restrict__ C,
    const int* __restrict__ rowsA, const int* __restrict__ rowsC,
    const float* __restrict__ wvec, int wstride,
    const float* __restrict__ addend,
    const float* __restrict__ ex1, const float* __restrict__ ex2,
    const float* __restrict__ pt, const float* __restrict__ tscale,
    const int* __restrict__ cntPtr,
    int M, int K, int N)
{
    int Mtot = cntPtr ? *cntPtr : M;
    int bm = blockIdx.y * BM;
    if (bm >= Mtot) return;
    int bn = blockIdx.x * BN;

    __shared__ __align__(16) float As[BKD * 132];
    __shared__ __align__(16) float Bs[BKD * 128];

    int tid = threadIdx.x;
    int aRow = tid >> 1;
    int aCol = (tid & 1) * 4;
    int gm = bm + aRow;
    bool aValid = (gm < Mtot);
    int arow_actual = aValid ? (rowsA ? rowsA[gm] : gm) : 0;
    const float* aPtr = A + (size_t)arow_actual * K + aCol;

    int bRow = tid >> 5;
    int bCol = (tid & 31) * 4;
    const float* bPtr = B + (size_t)bRow * N + bn + bCol;

    float acc[8][8];
    #pragma unroll
    for (int i = 0; i < 8; i++)
        #pragma unroll
        for (int j = 0; j < 8; j++) acc[i][j] = 0.f;

    int ty = tid >> 4, tx = tid & 15;

    for (int k0 = 0; k0 < K; k0 += BKD) {
        float4 av = aValid ? *(const float4*)(aPtr + k0) : make_float4(0.f, 0.f, 0.f, 0.f);
        float4 bv = *(const float4*)(bPtr + (size_t)k0 * N);
        __syncthreads();
        As[(aCol + 0) * 132 + aRow] = av.x;
        As[(aCol + 1) * 132 + aRow] = av.y;
        As[(aCol + 2) * 132 + aRow] = av.z;
        As[(aCol + 3) * 132 + aRow] = av.w;
        *(float4*)&Bs[bRow * 128 + bCol] = bv;
        __syncthreads();
        #pragma unroll
        for (int k = 0; k < BKD; k++) {
            float4 a0 = *(const float4*)&As[k * 132 + ty * 8];
            float4 a1 = *(const float4*)&As[k * 132 + ty * 8 + 4];
            float4 b0 = *(const float4*)&Bs[k * 128 + tx * 8];
            float4 b1 = *(const float4*)&Bs[k * 128 + tx * 8 + 4];
            float a[8] = {a0.x, a0.y, a0.z, a0.w, a1.x, a1.y, a1.z, a1.w};
            float b[8] = {b0.x, b0.y, b0.z, b0.w, b1.x, b1.y, b1.z, b1.w};
            #pragma unroll
            for (int i = 0; i < 8; i++)
                #pragma unroll
                for (int j = 0; j < 8; j++)
                    acc[i][j] = fmaf(a[i], b[j], acc[i][j]);
        }
    }

    #pragma unroll
    for (int i = 0; i < 8; i++) {
        int m = bm + ty * 8 + i;
        if (m >= Mtot) continue;
        int crow = m;
        float rw = 1.f, scale = 0.f;
        if (MODE == 1) {
            if (rowsC) crow = rowsC[m];
            rw = wvec[m * wstride];
        }
        if (MODE == 4) scale = tscale[0] * sqrtf(pt[m] + 1e-8f);
        #pragma unroll
        for (int j = 0; j < 8; j++) {
            int n = bn + tx * 8 + j;
            float v = acc[i][j] + bias[n];
            size_t idx = (size_t)crow * N + n;
            if (MODE == 0)      C[idx] = fmaxf(v, 0.f);
            else if (MODE == 1) C[idx] += rw * v;
            else if (MODE == 2) C[idx] = tanhf(v);
            else if (MODE == 3) C[idx] = addend[(size_t)m * N + n] + v;
            else if (MODE == 4) {
                float fd = tanhf(v);
                C[idx] = 0.5f * (ex1[idx] + ex2[idx]) + scale * fd;
            }
        }
    }
}

// ---------------------- repulsion / tension reductions ----------------------
__global__ __launch_bounds__(256) void rep_kernel() {
    int b = blockIdx.x;
    float ss = 0.f;
    for (int n = threadIdx.x; n < OUT_DIM; n += 256) {
        size_t i = (size_t)b * OUT_DIM + n;
        float r = g_out_p[i] - g_out_m[i];
        g_rep[i] = r;
        ss += r * r;
    }
    float tot = block_reduce_sum(ss);
    if (threadIdx.x == 0) g_pt[b] = tot;
}

__global__ __launch_bounds__(256) void sumsq_kernel() {
    int b = blockIdx.x;
    float ss = 0.f;
    for (int n = threadIdx.x; n < OUT_DIM; n += 256) {
        float r = g_mr[(size_t)b * OUT_DIM + n];
        ss += r * r;
    }
    float tot = block_reduce_sum(ss);
    if (threadIdx.x == 0) g_pt[b] = tot;
}

__global__ __launch_bounds__(256) void mean_kernel(const float* __restrict__ src,
                                                   float* __restrict__ dst) {
    float s = 0.f;
    for (int i = threadIdx.x; i < BATCH; i += 256) s += src[i];
    float tot = block_reduce_sum(s);
    if (threadIdx.x == 0) dst[0] = tot * (1.f / (float)BATCH);
}

// ------------------------- self-model hidden layer --------------------------
// h1[b,j] = tanh(si0*w1[0,j] + si1*w1[1,j] + si2*w1[2,j] + b1[j])
__global__ __launch_bounds__(256) void h1_kernel(const float* __restrict__ w1,
                                                 const float* __restrict__ b1,
                                                 int step) {
    int idx = blockIdx.x * blockDim.x + threadIdx.x;
    if (idx >= BATCH * HID_DIM) return;
    int b = idx >> 11;       // /2048
    int j = idx & 2047;
    float t  = g_pt[b];
    float d  = (step == 0) ? 0.f : (t - g_tens[step]);
    float sv = (float)step * (1.f / 3.f);
    float v = t * w1[j] + d * w1[HID_DIM + j] + sv * w1[2 * HID_DIM + j] + b1[j];
    g_h1[idx] = tanhf(v);
}

// ------------------------------ aux loss ------------------------------------
__global__ __launch_bounds__(256) void aux_kernel(float* __restrict__ out, int out_size) {
    float s = 0.f;
    for (int i = threadIdx.x; i < BATCH; i += 256) s += g_ent[i];
    float tot = block_reduce_sum(s);
    if (threadIdx.x == 0) {
        float h  = tot * (1.f / (float)BATCH);
        float el = (h - H_TARGET) * (h - H_TARGET);
        float conv = (fabsf(g_tens[1] - g_tens[0]) +
                      fabsf(g_tens[2] - g_tens[1]) +
                      fabsf(g_tens[3] - g_tens[2])) * (1.f / 3.f);
        float aux = el + 0.001f * conv;
        for (int j = BATCH * OUT_DIM; j < out_size; j++) out[j] = aux;
    }
}

// ------------------------------ launcher ------------------------------------
extern "C" void kernel_launch(void* const* d_in, const int* in_sizes, int n_in,
                              void* d_out, int out_size) {
    (void)in_sizes; (void)n_in;
    const float* x    = (const float*)d_in[0];
    const float* gaw  = (const float*)d_in[1];
    const float* gab  = (const float*)d_in[2];
    const float* wa1  = (const float*)d_in[3];
    const float* ba1  = (const float*)d_in[4];
    const float* wa2  = (const float*)d_in[5];
    const float* ba2  = (const float*)d_in[6];
    const float* ggw  = (const float*)d_in[7];
    const float* ggb  = (const float*)d_in[8];
    const float* wg1  = (const float*)d_in[9];
    const float* bg1  = (const float*)d_in[10];
    const float* wg2  = (const float*)d_in[11];
    const float* bg2  = (const float*)d_in[12];
    const float* smw1 = (const float*)d_in[13];
    const float* smb1 = (const float*)d_in[14];
    const float* smw2 = (const float*)d_in[15];
    const float* smb2 = (const float*)d_in[16];
    const float* siw  = (const float*)d_in[17];
    const float* sib  = (const float*)d_in[18];
    const float* ftw  = (const float*)d_in[19];
    const float* ftb  = (const float*)d_in[20];
    const float* tsc  = (const float*)d_in[21];
    float* out = (float*)d_out;

    float *p_h, *p_op, *p_om, *p_rep, *p_mr, *p_ss, *p_h1, *p_pt, *p_tens, *p_wg, *p_wcomp;
    int *p_cnt, *p_list;
    cudaGetSymbolAddress((void**)&p_h,     g_h);
    cudaGetSymbolAddress((void**)&p_op,    g_out_p);
    cudaGetSymbolAddress((void**)&p_om,    g_out_m);
    cudaGetSymbolAddress((void**)&p_rep,   g_rep);
    cudaGetSymbolAddress((void**)&p_mr,    g_mr);
    cudaGetSymbolAddress((void**)&p_ss,    g_ss);
    cudaGetSymbolAddress((void**)&p_h1,    g_h1);
    cudaGetSymbolAddress((void**)&p_pt,    g_pt);
    cudaGetSymbolAddress((void**)&p_tens,  g_tens);
    cudaGetSymbolAddress((void**)&p_wg,    g_wg);
    cudaGetSymbolAddress((void**)&p_wcomp, g_wcomp);
    cudaGetSymbolAddress((void**)&p_cnt,   g_cnt);
    cudaGetSymbolAddress((void**)&p_list,  g_list);

    zero_kernel<<<(BATCH * OUT_DIM + 255) / 256, 256>>>();
    gate_kernel<<<BATCH, 256>>>(x, gaw, gab, ggw, ggb);
    route_kernel<<<1, NEXPA * 32>>>();

    dim3 gH(HID_DIM / BN, BATCH / BM);   // N=2048 GEMMs
    dim3 gO(OUT_DIM / BN, BATCH / BM);   // N=1024 GEMMs

    // EngineA: routed experts
    for (int e = 0; e < NEXPA; e++) {
        gemm_k<0><<<gH, 256>>>(x, wa1 + (size_t)e * IN_DIM * HID_DIM, ba1 + e * HID_DIM,
                               p_h, p_list + e * BATCH, nullptr, nullptr, 0,
                               nullptr, nullptr, nullptr, nullptr, nullptr,
                               p_cnt + e, BATCH, IN_DIM, HID_DIM);
        gemm_k<1><<<gO, 256>>>(p_h, wa2 + (size_t)e * HID_DIM * OUT_DIM, ba2 + e * OUT_DIM,
                               p_op, nullptr, p_list + e * BATCH, p_wcomp + e * BATCH, 1,
                               nullptr, nullptr, nullptr, nullptr, nullptr,
                               p_cnt + e, BATCH, HID_DIM, OUT_DIM);
    }
    // EngineG: dense experts
    for (int e = 0; e < NEXPG; e++) {
        gemm_k<0><<<gH, 256>>>(x, wg1 + (size_t)e * IN_DIM * HID_DIM, bg1 + e * HID_DIM,
                               p_h, nullptr, nullptr, nullptr, 0,
                               nullptr, nullptr, nullptr, nullptr, nullptr,
                               nullptr, BATCH, IN_DIM, HID_DIM);
        gemm_k<1><<<gO, 256>>>(p_h, wg2 + (size_t)e * HID_DIM * OUT_DIM, bg2 + e * OUT_DIM,
                               p_om, nullptr, nullptr, p_wg + e, NEXPG,
                               nullptr, nullptr, nullptr, nullptr, nullptr,
                               nullptr, BATCH, HID_DIM, OUT_DIM);
    }

    rep_kernel<<<BATCH, 256>>>();
    mean_kernel<<<1, 256>>>(p_pt, p_tens + 0);

    for (int s = 0; s < 3; s++) {
        h1_kernel<<<(BATCH * HID_DIM + 255) / 256, 256>>>(smw1, smb1, s);
        gemm_k<2><<<gO, 256>>>(p_h1, smw2, smb2, p_ss,
                               nullptr, nullptr, nullptr, 0,
                               nullptr, nullptr, nullptr, nullptr, nullptr,
                               nullptr, BATCH, HID_DIM, OUT_DIM);
        gemm_k<3><<<gO, 256>>>(p_ss, siw, sib, p_mr,
                               nullptr, nullptr, nullptr, 0,
                               p_rep, nullptr, nullptr, nullptr, nullptr,
                               nullptr, BATCH, OUT_DIM, OUT_DIM);
        sumsq_kernel<<<BATCH, 256>>>();
        mean_kernel<<<1, 256>>>(p_pt, p_tens + s + 1);
    }

    gemm_k<4><<<gO, 256>>>(p_mr, ftw, ftb, out,
                           nullptr, nullptr, nullptr, 0,
                           nullptr, p_op, p_om, p_pt, tsc,
                           nullptr, BATCH, OUT_DIM, OUT_DIM);
    aux_kernel<<<1, 256>>>(out, out_size);
}

// round 4
// speedup vs baseline: 3.2541x; 3.2541x over previous
#include <cuda_runtime.h>
#include <cuda_bf16.h>
#include <cstdint>
#include <math.h>

#define BATCH   2048
#define IN_DIM  1024
#define HID_DIM 2048
#define OUT_DIM 1024
#define NEXPA   12
#define NEXPG   6
#define NEXP    18
#define H_TARGET 1.0114042647073518f

// GEMM tiling
#define BMT 128
#define BNT 128
#define BKT 32
#define RS  40                 // smem row stride in bf16 elems (80B, conflict-free)
#define STG_B (128 * RS * 2)   // one array, one stage, bytes = 10240
#define SMEM_TOT (8 * STG_B)   // Ah,Al,Bh,Bl x 2 stages = 81920

// ---------------- device scratch ----------------
__device__ __nv_bfloat16 c_xh[BATCH * IN_DIM],  c_xl[BATCH * IN_DIM];
__device__ __nv_bfloat16 c_hh[(size_t)NEXP * BATCH * HID_DIM];
__device__ __nv_bfloat16 c_hl[(size_t)NEXP * BATCH * HID_DIM];
__device__ float         g_o [(size_t)NEXP * BATCH * OUT_DIM];
__device__ __nv_bfloat16 c_w1h[(size_t)NEXP * HID_DIM * IN_DIM], c_w1l[(size_t)NEXP * HID_DIM * IN_DIM];
__device__ __nv_bfloat16 c_w2h[(size_t)NEXP * OUT_DIM * HID_DIM], c_w2l[(size_t)NEXP * OUT_DIM * HID_DIM];
__device__ __nv_bfloat16 c_smh[OUT_DIM * HID_DIM], c_sml[OUT_DIM * HID_DIM];
__device__ __nv_bfloat16 c_sih[OUT_DIM * OUT_DIM], c_sil[OUT_DIM * OUT_DIM];
__device__ __nv_bfloat16 c_fth[OUT_DIM * OUT_DIM], c_ftl[OUT_DIM * OUT_DIM];
__device__ __nv_bfloat16 c_h1h[BATCH * HID_DIM], c_h1l[BATCH * HID_DIM];
__device__ __nv_bfloat16 c_ssh[BATCH * OUT_DIM], c_ssl[BATCH * OUT_DIM];
__device__ __nv_bfloat16 c_mrh[BATCH * OUT_DIM], c_mrl[BATCH * OUT_DIM];
__device__ float g_out_p[BATCH * OUT_DIM], g_out_m[BATCH * OUT_DIM];
__device__ float g_rep[BATCH * OUT_DIM], g_mr[BATCH * OUT_DIM];
__device__ float g_wa[BATCH * NEXPA], g_wg[BATCH * NEXPG];
__device__ float g_ent[BATCH], g_pt[BATCH], g_tens[8];

// ---------------- small helpers ----------------
__device__ __forceinline__ float block_reduce_sum(float v) {
    __shared__ float s[32];
    int lane = threadIdx.x & 31, w = threadIdx.x >> 5;
    #pragma unroll
    for (int o = 16; o > 0; o >>= 1) v += __shfl_down_sync(0xffffffffu, v, o);
    if (lane == 0) s[w] = v;
    __syncthreads();
    v = (threadIdx.x < (blockDim.x >> 5)) ? s[threadIdx.x] : 0.f;
    if (w == 0)
        #pragma unroll
        for (int o = 16; o > 0; o >>= 1) v += __shfl_down_sync(0xffffffffu, v, o);
    return v;
}
__device__ __forceinline__ void split_bf16(float v, __nv_bfloat16& h, __nv_bfloat16& l) {
    h = __float2bfloat16(v);
    l = __float2bfloat16(v - __bfloat162float(h));
}
__device__ __forceinline__ uint32_t smem_u32(const void* p) {
    uint32_t a;
    asm("{ .reg .u64 t; cvta.to.shared.u64 t, %1; cvt.u32.u64 %0, t; }" : "=r"(a) : "l"(p));
    return a;
}
#define CP_ASYNC16(dst, src) \
    asm volatile("cp.async.ca.shared.global [%0], [%1], 16;" :: "r"(dst), "l"(src))
#define CP_COMMIT() asm volatile("cp.async.commit_group;")
#define CP_WAIT0()  asm volatile("cp.async.wait_group 0;")
#define LDM_X4(r0,r1,r2,r3,a) \
    asm volatile("ldmatrix.sync.aligned.m8n8.x4.shared.b16 {%0,%1,%2,%3}, [%4];" \
        : "=r"(r0), "=r"(r1), "=r"(r2), "=r"(r3) : "r"(a))
#define MMA16816(c, a, b) \
    asm volatile("mma.sync.aligned.m16n8k16.row.col.f32.bf16.bf16.f32 " \
        "{%0,%1,%2,%3}, {%4,%5,%6,%7}, {%8,%9}, {%0,%1,%2,%3};" \
        : "+f"((c)[0]), "+f"((c)[1]), "+f"((c)[2]), "+f"((c)[3]) \
        : "r"((a)[0]), "r"((a)[1]), "r"((a)[2]), "r"((a)[3]), "r"((b)[0]), "r"((b)[1]))

// ---------------- conversions ----------------
__global__ __launch_bounds__(256) void split_act(const float* __restrict__ src,
    __nv_bfloat16* __restrict__ h, __nv_bfloat16* __restrict__ l, int n) {
    int i = blockIdx.x * 256 + threadIdx.x;
    if (i < n) { __nv_bfloat16 hh, ll; split_bf16(src[i], hh, ll); h[i] = hh; l[i] = ll; }
}
// W[z][K][N] fp32 -> Wh/Wl[z][N][K] bf16
__global__ __launch_bounds__(256) void convert_w(const float* __restrict__ W,
    __nv_bfloat16* __restrict__ Wh, __nv_bfloat16* __restrict__ Wl, int K, int N) {
    __shared__ float t[32][33];
    size_t zo = (size_t)blockIdx.z * K * N;
    int k0 = blockIdx.y * 32, n0 = blockIdx.x * 32;
    int tx = threadIdx.x & 31, ty = threadIdx.x >> 5;
    #pragma unroll
    for (int i = 0; i < 4; i++)
        t[ty + i * 8][tx] = W[zo + (size_t)(k0 + ty + i * 8) * N + n0 + tx];
    __syncthreads();
    #pragma unroll
    for (int i = 0; i < 4; i++) {
        int n = n0 + ty + i * 8;
        __nv_bfloat16 h, l; split_bf16(t[tx][ty + i * 8], h, l);
        Wh[zo + (size_t)n * K + k0 + tx] = h;
        Wl[zo + (size_t)n * K + k0 + tx] = l;
    }
}

// ---------------- gating ----------------
__global__ __launch_bounds__(256) void gate_kernel(
    const float* __restrict__ x, const float* __restrict__ gaw, const float* __restrict__ gab,
    const float* __restrict__ ggw, const float* __restrict__ ggb) {
    int b = blockIdx.x, tid = threadIdx.x;
    float acc[18];
    #pragma unroll
    for (int e = 0; e < 18; e++) acc[e] = 0.f;
    const float* xr = x + (size_t)b * IN_DIM;
    for (int i = tid; i < IN_DIM; i += 256) {
        float xv = xr[i];
        #pragma unroll
        for (int e = 0; e < NEXPA; e++) acc[e] = fmaf(xv, gaw[i * NEXPA + e], acc[e]);
        #pragma unroll
        for (int e = 0; e < NEXPG; e++) acc[12 + e] = fmaf(xv, ggw[i * NEXPG + e], acc[12 + e]);
    }
    __shared__ float s[18][8];
    int lane = tid & 31, w = tid >> 5;
    #pragma unroll
    for (int e = 0; e < 18; e++) {
        float v = acc[e];
        #pragma unroll
        for (int o = 16; o > 0; o >>= 1) v += __shfl_down_sync(0xffffffffu, v, o);
        if (lane == 0) s[e][w] = v;
    }
    __syncthreads();
    if (tid == 0) {
        float lg[18];
        for (int e = 0; e < 18; e++) {
            float v = 0.f;
            for (int ww = 0; ww < 8; ww++) v += s[e][ww];
            lg[e] = v + (e < 12 ? gab[e] : ggb[e - 12]);
        }
        bool used[NEXPA] = {false};
        int idxs[4]; float vals[4];
        for (int k = 0; k < 4; k++) {
            int bi = -1; float bv = -INFINITY;
            for (int e = 0; e < NEXPA; e++)
                if (!used[e] && lg[e] > bv) { bv = lg[e]; bi = e; }
            used[bi] = true; idxs[k] = bi; vals[k] = bv;
        }
        float m = vals[0], sum = 0.f, wv[4];
        for (int k = 0; k < 4; k++) { wv[k] = expf(vals[k] - m); sum += wv[k]; }
        for (int e = 0; e < NEXPA; e++) g_wa[b * NEXPA + e] = 0.f;
        for (int k = 0; k < 4; k++) g_wa[b * NEXPA + idxs[k]] = wv[k] / sum;
        float mg = -INFINITY;
        for (int e = 0; e < NEXPG; e++) mg = fmaxf(mg, lg[12 + e]);
        float sg = 0.f, eg[NEXPG];
        for (int e = 0; e < NEXPG; e++) { eg[e] = expf(lg[12 + e] - mg); sg += eg[e]; }
        float ent = 0.f;
        for (int e = 0; e < NEXPG; e++) {
            float wge = eg[e] / sg;
            g_wg[b * NEXPG + e] = wge;
            ent -= wge * logf(wge + 1e-8f);
        }
        g_ent[b] = ent;
    }
}

// ---------------- mma.sync GEMM ----------------
// C[z][M,N] = epi(A[z][M,K] @ B[z][N,K]^T + bias)
// MODE 0: relu -> bf16 pair.  1: fp32.  2: tanh -> pair.  3: addend+v -> fp32+pair.  4: final -> fp32.
template<int MODE>
__global__ __launch_bounds__(256, 1) void tgemm(
    const __nv_bfloat16* __restrict__ Ah, const __nv_bfloat16* __restrict__ Al, long long sAz,
    const __nv_bfloat16* __restrict__ Bh, const __nv_bfloat16* __restrict__ Bl, long long sBz,
    const float* __restrict__ bias, int sBias,
    float* __restrict__ Cf, long long sCfz,
    __nv_bfloat16* __restrict__ Ch, __nv_bfloat16* __restrict__ Cl, long long sCpz,
    const float* __restrict__ addend, const float* __restrict__ ex1, const float* __restrict__ ex2,
    const float* __restrict__ pt, const float* __restrict__ tscale,
    int K, int N)
{
    extern __shared__ char smem[];
    int z = blockIdx.z;
    int bm = blockIdx.y * BMT, bn = blockIdx.x * BNT;
    int tid = threadIdx.x, lane = tid & 31, wid = tid >> 5;
    int wm = (wid & 3) * 32, wn = (wid >> 2) * 64;
    uint32_t sb = smem_u32(smem);
    // stage base offsets (bytes): [Ah Al Bh Bl][stage]
    const uint32_t oAh = 0, oAl = 2 * STG_B, oBh = 4 * STG_B, oBl = 6 * STG_B;

    const __nv_bfloat16* gAh = Ah + (size_t)z * sAz;
    const __nv_bfloat16* gAl = Al + (size_t)z * sAz;
    const __nv_bfloat16* gBh = Bh + (size_t)z * sBz;
    const __nv_bfloat16* gBl = Bl + (size_t)z * sBz;

    // cp.async mapping: chunk c in [0,512): row=c>>2, ko=(c&3)*8 elems
    int c0i = tid, c1i = tid + 256;
    int r0 = c0i >> 2, o0 = (c0i & 3) * 8;
    int r1 = c1i >> 2, o1 = (c1i & 3) * 8;

    float cacc[2][8][4];
    #pragma unroll
    for (int i = 0; i < 2; i++)
        #pragma unroll
        for (int j = 0; j < 8; j++)
            #pragma unroll
            for (int q = 0; q < 4; q++) cacc[i][j][q] = 0.f;

    int nIter = K >> 5;
    auto load_stage = [&](int it) {
        int p = it & 1;
        uint32_t dst;
        size_t k0 = (size_t)it * BKT;
        dst = sb + oAh + p * STG_B + (r0 * RS + o0) * 2;
        CP_ASYNC16(dst, gAh + (size_t)(bm + r0) * K + k0 + o0);
        dst = sb + oAh + p * STG_B + (r1 * RS + o1) * 2;
        CP_ASYNC16(dst, gAh + (size_t)(bm + r1) * K + k0 + o1);
        dst = sb + oAl + p * STG_B + (r0 * RS + o0) * 2;
        CP_ASYNC16(dst, gAl + (size_t)(bm + r0) * K + k0 + o0);
        dst = sb + oAl + p * STG_B + (r1 * RS + o1) * 2;
        CP_ASYNC16(dst, gAl + (size_t)(bm + r1) * K + k0 + o1);
        dst = sb + oBh + p * STG_B + (r0 * RS + o0) * 2;
        CP_ASYNC16(dst, gBh + (size_t)(bn + r0) * K + k0 + o0);
        dst = sb + oBh + p * STG_B + (r1 * RS + o1) * 2;
        CP_ASYNC16(dst, gBh + (size_t)(bn + r1) * K + k0 + o1);
        dst = sb + oBl + p * STG_B + (r0 * RS + o0) * 2;
        CP_ASYNC16(dst, gBl + (size_t)(bn + r0) * K + k0 + o0);
        dst = sb + oBl + p * STG_B + (r1 * RS + o1) * 2;
        CP_ASYNC16(dst, gBl + (size_t)(bn + r1) * K + k0 + o1);
        CP_COMMIT();
    };

    load_stage(0);
    // ldmatrix per-thread base addresses (stage 0, ks 0)
    int arow = wm + (lane & 15);                  // + mt*16
    int acolb = (lane >> 4) * 16;                 // bytes (8 elems)
    int brow = wn + (lane & 7) + ((lane >> 4) << 3);  // + np*16
    int bcolb = ((lane >> 3) & 1) * 16;

    for (int it = 0; it < nIter; it++) {
        int p = it & 1;
        CP_WAIT0();
        __syncthreads();
        if (it + 1 < nIter) load_stage(it + 1);

        uint32_t aBh = sb + oAh + p * STG_B, aBl_ = sb + oAl + p * STG_B;
        uint32_t bBh = sb + oBh + p * STG_B, bBl_ = sb + oBl + p * STG_B;
        #pragma unroll
        for (int ks = 0; ks < 2; ks++) {
            uint32_t af[2][2][4], bf[2][8][2];
            #pragma unroll
            for (int mt = 0; mt < 2; mt++) {
                uint32_t off = ((arow + mt * 16) * RS) * 2 + ks * 32 + acolb;
                LDM_X4(af[0][mt][0], af[0][mt][1], af[0][mt][2], af[0][mt][3], aBh + off);
                LDM_X4(af[1][mt][0], af[1][mt][1], af[1][mt][2], af[1][mt][3], aBl_ + off);
            }
            #pragma unroll
            for (int np = 0; np < 4; np++) {
                uint32_t off = ((brow + np * 16) * RS) * 2 + ks * 32 + bcolb;
                uint32_t t0, t1, t2, t3;
                LDM_X4(t0, t1, t2, t3, bBh + off);
                bf[0][np * 2][0] = t0; bf[0][np * 2][1] = t1;
                bf[0][np * 2 + 1][0] = t2; bf[0][np * 2 + 1][1] = t3;
                LDM_X4(t0, t1, t2, t3, bBl_ + off);
                bf[1][np * 2][0] = t0; bf[1][np * 2][1] = t1;
                bf[1][np * 2 + 1][0] = t2; bf[1][np * 2 + 1][1] = t3;
            }
            #pragma unroll
            for (int mt = 0; mt < 2; mt++)
                #pragma unroll
                for (int nt = 0; nt < 8; nt++) {
                    MMA16816(cacc[mt][nt], af[0][mt], bf[0][nt]);
                    MMA16816(cacc[mt][nt], af[0][mt], bf[1][nt]);
                    MMA16816(cacc[mt][nt], af[1][mt], bf[0][nt]);
                }
        }
        __syncthreads();
    }

    // epilogue
    int gid = lane >> 2, tig = lane & 3;
    const float* bz = bias + (size_t)z * sBias;
    float* Cfz = (MODE != 0 && MODE != 2) ? Cf + (size_t)z * sCfz : nullptr;
    __nv_bfloat16* Chz = (MODE == 0 || MODE == 2 || MODE == 3) ? Ch + (size_t)z * sCpz : nullptr;
    __nv_bfloat16* Clz = (MODE == 0 || MODE == 2 || MODE == 3) ? Cl + (size_t)z * sCpz : nullptr;
    #pragma unroll
    for (int mt = 0; mt < 2; mt++) {
        int m0 = bm + wm + mt * 16 + gid;
        float s0 = 0.f, s8 = 0.f;
        if (MODE == 4) {
            float ts = tscale[0];
            s0 = ts * sqrtf(pt[m0] + 1e-8f);
            s8 = ts * sqrtf(pt[m0 + 8] + 1e-8f);
        }
        #pragma unroll
        for (int nt = 0; nt < 8; nt++) {
            int n0 = bn + wn + nt * 8 + tig * 2;
            float b0v = bz[n0], b1v = bz[n0 + 1];
            #pragma unroll
            for (int rr = 0; rr < 2; rr++) {
                int m = m0 + rr * 8;
                float v0 = cacc[mt][nt][rr * 2 + 0] + b0v;
                float v1 = cacc[mt][nt][rr * 2 + 1] + b1v;
                size_t idx = (size_t)m * N + n0;
                if (MODE == 0) { v0 = fmaxf(v0, 0.f); v1 = fmaxf(v1, 0.f); }
                else if (MODE == 2) { v0 = tanhf(v0); v1 = tanhf(v1); }
                else if (MODE == 3) {
                    float2 ad = *(const float2*)(addend + idx);
                    v0 += ad.x; v1 += ad.y;
                    *(float2*)(Cfz + idx) = make_float2(v0, v1);
                } else if (MODE == 4) {
                    float2 e1 = *(const float2*)(ex1 + idx);
                    float2 e2 = *(const float2*)(ex2 + idx);
                    float sc = rr ? s8 : s0;
                    *(float2*)(Cfz + idx) = make_float2(
                        0.5f * (e1.x + e2.x) + sc * tanhf(v0),
                        0.5f * (e1.y + e2.y) + sc * tanhf(v1));
                } else { // MODE 1
                    *(float2*)(Cfz + idx) = make_float2(v0, v1);
                }
                if (MODE == 0 || MODE == 2 || MODE == 3) {
                    __nv_bfloat16 h0, l0, h1, l1;
                    split_bf16(v0, h0, l0); split_bf16(v1, h1, l1);
                    *(__nv_bfloat162*)(Chz + idx) = __nv_bfloat162(h0, h1);
                    *(__nv_bfloat162*)(Clz + idx) = __nv_bfloat162(l0, l1);
                }
            }
        }
    }
}

// ---------------- combine + reductions ----------------
__global__ __launch_bounds__(256) void combine_kernel() {
    int b = blockIdx.x, tid = threadIdx.x;
    __shared__ float wA[NEXPA], wG[NEXPG];
    if (tid < NEXPA) wA[tid] = g_wa[b * NEXPA + tid];
    if (tid < NEXPG) wG[tid] = g_wg[b * NEXPG + tid];
    __syncthreads();
    float ss = 0.f;
    for (int n = tid; n < OUT_DIM; n += 256) {
        float op = 0.f, om = 0.f;
        #pragma unroll
        for (int e = 0; e < NEXPA; e++)
            op += wA[e] * g_o[((size_t)e * BATCH + b) * OUT_DIM + n];
        #pragma unroll
        for (int e = 0; e < NEXPG; e++)
            om += wG[e] * g_o[((size_t)(12 + e) * BATCH + b) * OUT_DIM + n];
        size_t i = (size_t)b * OUT_DIM + n;
        g_out_p[i] = op; g_out_m[i] = om;
        float r = op - om;
        g_rep[i] = r; ss += r * r;
    }
    float tot = block_reduce_sum(ss);
    if (tid == 0) g_pt[b] = tot;
}
__global__ __launch_bounds__(256) void sumsq_kernel() {
    int b = blockIdx.x;
    float ss = 0.f;
    for (int n = threadIdx.x; n < OUT_DIM; n += 256) {
        float r = g_mr[(size_t)b * OUT_DIM + n];
        ss += r * r;
    }
    float tot = block_reduce_sum(ss);
    if (threadIdx.x == 0) g_pt[b] = tot;
}
__global__ __launch_bounds__(256) void mean_kernel(const float* __restrict__ src, float* __restrict__ dst) {
    float s = 0.f;
    for (int i = threadIdx.x; i < BATCH; i += 256) s += src[i];
    float tot = block_reduce_sum(s);
    if (threadIdx.x == 0) dst[0] = tot * (1.f / (float)BATCH);
}
__global__ __launch_bounds__(256) void h1_kernel(const float* __restrict__ w1,
                                                 const float* __restrict__ b1, int step) {
    int idx = blockIdx.x * blockDim.x + threadIdx.x;
    if (idx >= BATCH * HID_DIM) return;
    int b = idx >> 11, j = idx & 2047;
    float t = g_pt[b];
    float d = (step == 0) ? 0.f : (t - g_tens[step]);
    float sv = (float)step * (1.f / 3.f);
    float v = tanhf(t * w1[j] + d * w1[HID_DIM + j] + sv * w1[2 * HID_DIM + j] + b1[j]);
    __nv_bfloat16 h, l; split_bf16(v, h, l);
    c_h1h[idx] = h; c_h1l[idx] = l;
}
__global__ __launch_bounds__(256) void aux_kernel(float* __restrict__ out, int out_size) {
    float s = 0.f;
    for (int i = threadIdx.x; i < BATCH; i += 256) s += g_ent[i];
    float tot = block_reduce_sum(s);
    if (threadIdx.x == 0) {
        float h = tot * (1.f / (float)BATCH);
        float el = (h - H_TARGET) * (h - H_TARGET);
        float conv = (fabsf(g_tens[1] - g_tens[0]) + fabsf(g_tens[2] - g_tens[1]) +
                      fabsf(g_tens[3] - g_tens[2])) * (1.f / 3.f);
        float aux = el + 0.001f * conv;
        for (int j = BATCH * OUT_DIM; j < out_size; j++) out[j] = aux;
    }
}

// ---------------- launcher ----------------
extern "C" void kernel_launch(void* const* d_in, const int* in_sizes, int n_in,
                              void* d_out, int out_size) {
    (void)in_sizes; (void)n_in;
    const float* x    = (const float*)d_in[0];
    const float* gaw  = (const float*)d_in[1];
    const float* gab  = (const float*)d_in[2];
    const float* wa1  = (const float*)d_in[3];
    const float* ba1  = (const float*)d_in[4];
    const float* wa2  = (const float*)d_in[5];
    const float* ba2  = (const float*)d_in[6];
    const float* ggw  = (const float*)d_in[7];
    const float* ggb  = (const float*)d_in[8];
    const float* wg1  = (const float*)d_in[9];
    const float* bg1  = (const float*)d_in[10];
    const float* wg2  = (const float*)d_in[11];
    const float* bg2  = (const float*)d_in[12];
    const float* smw1 = (const float*)d_in[13];
    const float* smb1 = (const float*)d_in[14];
    const float* smw2 = (const float*)d_in[15];
    const float* smb2 = (const float*)d_in[16];
    const float* siw  = (const float*)d_in[17];
    const float* sib  = (const float*)d_in[18];
    const float* ftw  = (const float*)d_in[19];
    const float* ftb  = (const float*)d_in[20];
    const float* tsc  = (const float*)d_in[21];
    float* out = (float*)d_out;

    cudaFuncSetAttribute(tgemm<0>, cudaFuncAttributeMaxDynamicSharedMemorySize, SMEM_TOT);
    cudaFuncSetAttribute(tgemm<1>, cudaFuncAttributeMaxDynamicSharedMemorySize, SMEM_TOT);
    cudaFuncSetAttribute(tgemm<2>, cudaFuncAttributeMaxDynamicSharedMemorySize, SMEM_TOT);
    cudaFuncSetAttribute(tgemm<3>, cudaFuncAttributeMaxDynamicSharedMemorySize, SMEM_TOT);
    cudaFuncSetAttribute(tgemm<4>, cudaFuncAttributeMaxDynamicSharedMemorySize, SMEM_TOT);

    __nv_bfloat16 *p_xh, *p_xl, *p_hh, *p_hl, *p_w1h, *p_w1l, *p_w2h, *p_w2l;
    __nv_bfloat16 *p_smh, *p_sml, *p_sih, *p_sil, *p_fth, *p_ftl;
    __nv_bfloat16 *p_h1h, *p_h1l, *p_ssh, *p_ssl, *p_mrh, *p_mrl;
    float *p_o, *p_op, *p_om, *p_rep, *p_mr, *p_pt, *p_tens;
    cudaGetSymbolAddress((void**)&p_xh, c_xh);   cudaGetSymbolAddress((void**)&p_xl, c_xl);
    cudaGetSymbolAddress((void**)&p_hh, c_hh);   cudaGetSymbolAddress((void**)&p_hl, c_hl);
    cudaGetSymbolAddress((void**)&p_w1h, c_w1h); cudaGetSymbolAddress((void**)&p_w1l, c_w1l);
    cudaGetSymbolAddress((void**)&p_w2h, c_w2h); cudaGetSymbolAddress((void**)&p_w2l, c_w2l);
    cudaGetSymbolAddress((void**)&p_smh, c_smh); cudaGetSymbolAddress((void**)&p_sml, c_sml);
    cudaGetSymbolAddress((void**)&p_sih, c_sih); cudaGetSymbolAddress((void**)&p_sil, c_sil);
    cudaGetSymbolAddress((void**)&p_fth, c_fth); cudaGetSymbolAddress((void**)&p_ftl, c_ftl);
    cudaGetSymbolAddress((void**)&p_h1h, c_h1h); cudaGetSymbolAddress((void**)&p_h1l, c_h1l);
    cudaGetSymbolAddress((void**)&p_ssh, c_ssh); cudaGetSymbolAddress((void**)&p_ssl, c_ssl);
    cudaGetSymbolAddress((void**)&p_mrh, c_mrh); cudaGetSymbolAddress((void**)&p_mrl, c_mrl);
    cudaGetSymbolAddress((void**)&p_o, g_o);     cudaGetSymbolAddress((void**)&p_op, g_out_p);
    cudaGetSymbolAddress((void**)&p_om, g_out_m); cudaGetSymbolAddress((void**)&p_rep, g_rep);
    cudaGetSymbolAddress((void**)&p_mr, g_mr);   cudaGetSymbolAddress((void**)&p_pt, g_pt);
    cudaGetSymbolAddress((void**)&p_tens, g_tens);

    // weight + activation conversion
    convert_w<<<dim3(HID_DIM/32, IN_DIM/32, 12), 256>>>(wa1, p_w1h, p_w1l, IN_DIM, HID_DIM);
    convert_w<<<dim3(HID_DIM/32, IN_DIM/32, 6), 256>>>(wg1, p_w1h + (size_t)12*HID_DIM*IN_DIM,
                                                       p_w1l + (size_t)12*HID_DIM*IN_DIM, IN_DIM, HID_DIM);
    convert_w<<<dim3(OUT_DIM/32, HID_DIM/32, 12), 256>>>(wa2, p_w2h, p_w2l, HID_DIM, OUT_DIM);
    convert_w<<<dim3(OUT_DIM/32, HID_DIM/32, 6), 256>>>(wg2, p_w2h + (size_t)12*OUT_DIM*HID_DIM,
                                                        p_w2l + (size_t)12*OUT_DIM*HID_DIM, HID_DIM, OUT_DIM);
    convert_w<<<dim3(OUT_DIM/32, HID_DIM/32, 1), 256>>>(smw2, p_smh, p_sml, HID_DIM, OUT_DIM);
    convert_w<<<dim3(OUT_DIM/32, OUT_DIM/32, 1), 256>>>(siw, p_sih, p_sil, OUT_DIM, OUT_DIM);
    convert_w<<<dim3(OUT_DIM/32, OUT_DIM/32, 1), 256>>>(ftw, p_fth, p_ftl, OUT_DIM, OUT_DIM);
    split_act<<<(BATCH*IN_DIM+255)/256, 256>>>(x, p_xh, p_xl, BATCH*IN_DIM);

    gate_kernel<<<BATCH, 256>>>(x, gaw, gab, ggw, ggb);

    dim3 gL1(HID_DIM/BNT, BATCH/BMT, 12), gL1g(HID_DIM/BNT, BATCH/BMT, 6);
    dim3 gL2(OUT_DIM/BNT, BATCH/BMT, 12), gL2g(OUT_DIM/BNT, BATCH/BMT, 6);
    dim3 g1(OUT_DIM/BNT, BATCH/BMT, 1);
    long long sW1 = (long long)HID_DIM*IN_DIM, sW2 = (long long)OUT_DIM*HID_DIM;
    long long sH = (long long)BATCH*HID_DIM, sO = (long long)BATCH*OUT_DIM;

    // layer 1 (relu -> pair)
    tgemm<0><<<gL1, 256, SMEM_TOT>>>(p_xh, p_xl, 0, p_w1h, p_w1l, sW1, ba1, HID_DIM,
        nullptr, 0, p_hh, p_hl, sH, nullptr, nullptr, nullptr, nullptr, nullptr, IN_DIM, HID_DIM);
    tgemm<0><<<gL1g, 256, SMEM_TOT>>>(p_xh, p_xl, 0, p_w1h + 12*sW1, p_w1l + 12*sW1, sW1, bg1, HID_DIM,
        nullptr, 0, p_hh + 12*sH, p_hl + 12*sH, sH, nullptr, nullptr, nullptr, nullptr, nullptr, IN_DIM, HID_DIM);
    // layer 2 (fp32 expert outs)
    tgemm<1><<<gL2, 256, SMEM_TOT>>>(p_hh, p_hl, sH, p_w2h, p_w2l, sW2, ba2, OUT_DIM,
        p_o, sO, nullptr, nullptr, 0, nullptr, nullptr, nullptr, nullptr, nullptr, HID_DIM, OUT_DIM);
    tgemm<1><<<gL2g, 256, SMEM_TOT>>>(p_hh + 12*sH, p_hl + 12*sH, sH, p_w2h + 12*sW2, p_w2l + 12*sW2, sW2,
        bg2, OUT_DIM, p_o + 12*sO, sO, nullptr, nullptr, 0, nullptr, nullptr, nullptr, nullptr, nullptr, HID_DIM, OUT_DIM);

    combine_kernel<<<BATCH, 256>>>();
    mean_kernel<<<1, 256>>>(p_pt, p_tens);

    for (int s = 0; s < 3; s++) {
        h1_kernel<<<(BATCH*HID_DIM+255)/256, 256>>>(smw1, smb1, s);
        tgemm<2><<<g1, 256, SMEM_TOT>>>(p_h1h, p_h1l, 0, p_smh, p_sml, 0, smb2, 0,
            nullptr, 0, p_ssh, p_ssl, 0, nullptr, nullptr, nullptr, nullptr, nullptr, HID_DIM, OUT_DIM);
        tgemm<3><<<g1, 256, SMEM_TOT>>>(p_ssh, p_ssl, 0, p_sih, p_sil, 0, sib, 0,
            p_mr, 0, p_mrh, p_mrl, 0, p_rep, nullptr, nullptr, nullptr, nullptr, OUT_DIM, OUT_DIM);
        sumsq_kernel<<<BATCH, 256>>>();
        mean_kernel<<<1, 256>>>(p_pt, p_tens + s + 1);
    }

    tgemm<4><<<g1, 256, SMEM_TOT>>>(p_mrh, p_mrl, 0, p_fth, p_ftl, 0, ftb, 0,
        out, 0, nullptr, nullptr, 0, nullptr, p_op, p_om, p_pt, tsc, OUT_DIM, OUT_DIM);
    aux_kernel<<<1, 256>>>(out, out_size);
}

// round 5
// speedup vs baseline: 4.8537x; 1.4916x over previous
#include <cuda_runtime.h>
#include <cuda_bf16.h>
#include <cstdint>
#include <math.h>

#define BATCH   2048
#define IN_DIM  1024
#define HID_DIM 2048
#define OUT_DIM 1024
#define NEXPA   12
#define NEXPG   6
#define NEXP    18
#define H_TARGET 1.0114042647073518f

#define BMT 128
#define BNT 128
#define BKT 32
#define RS  40
#define STG_B (128 * RS * 2)
#define SMEM_TOT (8 * STG_B)

// ---------------- device scratch ----------------
__device__ __nv_bfloat16 c_xh[BATCH * IN_DIM],  c_xl[BATCH * IN_DIM];
__device__ __nv_bfloat16 c_hh[(size_t)NEXP * BATCH * HID_DIM];
__device__ __nv_bfloat16 c_hl[(size_t)NEXP * BATCH * HID_DIM];
__device__ float         g_o [(size_t)NEXP * BATCH * OUT_DIM];
__device__ __nv_bfloat16 c_w1h[(size_t)NEXP * HID_DIM * IN_DIM], c_w1l[(size_t)NEXP * HID_DIM * IN_DIM];
__device__ __nv_bfloat16 c_w2h[(size_t)NEXP * OUT_DIM * HID_DIM], c_w2l[(size_t)NEXP * OUT_DIM * HID_DIM];
__device__ __nv_bfloat16 c_smh[OUT_DIM * HID_DIM], c_sml[OUT_DIM * HID_DIM];
__device__ __nv_bfloat16 c_sih[OUT_DIM * OUT_DIM], c_sil[OUT_DIM * OUT_DIM];
__device__ __nv_bfloat16 c_fth[OUT_DIM * OUT_DIM], c_ftl[OUT_DIM * OUT_DIM];
__device__ __nv_bfloat16 c_h1h[BATCH * HID_DIM], c_h1l[BATCH * HID_DIM];
__device__ __nv_bfloat16 c_ssh[BATCH * OUT_DIM], c_ssl[BATCH * OUT_DIM];
__device__ __nv_bfloat16 c_mrh[BATCH * OUT_DIM], c_mrl[BATCH * OUT_DIM];
__device__ float g_out_p[BATCH * OUT_DIM], g_out_m[BATCH * OUT_DIM];
__device__ float g_rep[BATCH * OUT_DIM], g_mr[BATCH * OUT_DIM];
__device__ float g_wa[BATCH * NEXPA], g_wg[BATCH * NEXPG];
__device__ float g_ent[BATCH], g_pt[BATCH], g_tens[8];
__device__ int   g_cnt[NEXPA];             // routed count per A expert
__device__ int   g_list[NEXPA * BATCH];    // expert slot -> token
__device__ int   g_posOf[NEXPA * BATCH];   // token -> expert slot

// ---------------- helpers ----------------
__device__ __forceinline__ float block_reduce_sum(float v) {
    __shared__ float s[32];
    int lane = threadIdx.x & 31, w = threadIdx.x >> 5;
    #pragma unroll
    for (int o = 16; o > 0; o >>= 1) v += __shfl_down_sync(0xffffffffu, v, o);
    if (lane == 0) s[w] = v;
    __syncthreads();
    v = (threadIdx.x < (blockDim.x >> 5)) ? s[threadIdx.x] : 0.f;
    if (w == 0)
        #pragma unroll
        for (int o = 16; o > 0; o >>= 1) v += __shfl_down_sync(0xffffffffu, v, o);
    return v;
}
__device__ __forceinline__ void split_bf16(float v, __nv_bfloat16& h, __nv_bfloat16& l) {
    h = __float2bfloat16(v);
    l = __float2bfloat16(v - __bfloat162float(h));
}
__device__ __forceinline__ uint32_t smem_u32(const void* p) {
    uint32_t a;
    asm("{ .reg .u64 t; cvta.to.shared.u64 t, %1; cvt.u32.u64 %0, t; }" : "=r"(a) : "l"(p));
    return a;
}
#define CP_ASYNC16(dst, src) \
    asm volatile("cp.async.ca.shared.global [%0], [%1], 16;" :: "r"(dst), "l"(src))
#define CP_COMMIT() asm volatile("cp.async.commit_group;")
#define CP_WAIT0()  asm volatile("cp.async.wait_group 0;")
#define LDM_X4(r0,r1,r2,r3,a) \
    asm volatile("ldmatrix.sync.aligned.m8n8.x4.shared.b16 {%0,%1,%2,%3}, [%4];" \
        : "=r"(r0), "=r"(r1), "=r"(r2), "=r"(r3) : "r"(a))
#define MMA16816(c, a, b) \
    asm volatile("mma.sync.aligned.m16n8k16.row.col.f32.bf16.bf16.f32 " \
        "{%0,%1,%2,%3}, {%4,%5,%6,%7}, {%8,%9}, {%0,%1,%2,%3};" \
        : "+f"((c)[0]), "+f"((c)[1]), "+f"((c)[2]), "+f"((c)[3]) \
        : "r"((a)[0]), "r"((a)[1]), "r"((a)[2]), "r"((a)[3]), "r"((b)[0]), "r"((b)[1]))

// ---------------- conversions ----------------
__global__ __launch_bounds__(256) void split_act(const float* __restrict__ src,
    __nv_bfloat16* __restrict__ h, __nv_bfloat16* __restrict__ l, int n) {
    int i = blockIdx.x * 256 + threadIdx.x;
    if (i < n) { __nv_bfloat16 hh, ll; split_bf16(src[i], hh, ll); h[i] = hh; l[i] = ll; }
}
__global__ __launch_bounds__(256) void convert_w(const float* __restrict__ W,
    __nv_bfloat16* __restrict__ Wh, __nv_bfloat16* __restrict__ Wl, int K, int N) {
    __shared__ float t[32][33];
    size_t zo = (size_t)blockIdx.z * K * N;
    int k0 = blockIdx.y * 32, n0 = blockIdx.x * 32;
    int tx = threadIdx.x & 31, ty = threadIdx.x >> 5;
    #pragma unroll
    for (int i = 0; i < 4; i++)
        t[ty + i * 8][tx] = W[zo + (size_t)(k0 + ty + i * 8) * N + n0 + tx];
    __syncthreads();
    #pragma unroll
    for (int i = 0; i < 4; i++) {
        int n = n0 + ty + i * 8;
        __nv_bfloat16 h, l; split_bf16(t[tx][ty + i * 8], h, l);
        Wh[zo + (size_t)n * K + k0 + tx] = h;
        Wl[zo + (size_t)n * K + k0 + tx] = l;
    }
}

// ---------------- gating + routing ----------------
__global__ __launch_bounds__(256) void gate_kernel(
    const float* __restrict__ x, const float* __restrict__ gaw, const float* __restrict__ gab,
    const float* __restrict__ ggw, const float* __restrict__ ggb) {
    int b = blockIdx.x, tid = threadIdx.x;
    float acc[18];
    #pragma unroll
    for (int e = 0; e < 18; e++) acc[e] = 0.f;
    const float* xr = x + (size_t)b * IN_DIM;
    for (int i = tid; i < IN_DIM; i += 256) {
        float xv = xr[i];
        #pragma unroll
        for (int e = 0; e < NEXPA; e++) acc[e] = fmaf(xv, gaw[i * NEXPA + e], acc[e]);
        #pragma unroll
        for (int e = 0; e < NEXPG; e++) acc[12 + e] = fmaf(xv, ggw[i * NEXPG + e], acc[12 + e]);
    }
    __shared__ float s[18][8];
    int lane = tid & 31, w = tid >> 5;
    #pragma unroll
    for (int e = 0; e < 18; e++) {
        float v = acc[e];
        #pragma unroll
        for (int o = 16; o > 0; o >>= 1) v += __shfl_down_sync(0xffffffffu, v, o);
        if (lane == 0) s[e][w] = v;
    }
    __syncthreads();
    if (tid == 0) {
        float lg[18];
        for (int e = 0; e < 18; e++) {
            float v = 0.f;
            for (int ww = 0; ww < 8; ww++) v += s[e][ww];
            lg[e] = v + (e < 12 ? gab[e] : ggb[e - 12]);
        }
        bool used[NEXPA] = {false};
        int idxs[4]; float vals[4];
        for (int k = 0; k < 4; k++) {
            int bi = -1; float bv = -INFINITY;
            for (int e = 0; e < NEXPA; e++)
                if (!used[e] && lg[e] > bv) { bv = lg[e]; bi = e; }
            used[bi] = true; idxs[k] = bi; vals[k] = bv;
        }
        float m = vals[0], sum = 0.f, wv[4];
        for (int k = 0; k < 4; k++) { wv[k] = expf(vals[k] - m); sum += wv[k]; }
        for (int e = 0; e < NEXPA; e++) g_wa[b * NEXPA + e] = 0.f;
        for (int k = 0; k < 4; k++) g_wa[b * NEXPA + idxs[k]] = wv[k] / sum;
        float mg = -INFINITY;
        for (int e = 0; e < NEXPG; e++) mg = fmaxf(mg, lg[12 + e]);
        float sg = 0.f, eg[NEXPG];
        for (int e = 0; e < NEXPG; e++) { eg[e] = expf(lg[12 + e] - mg); sg += eg[e]; }
        float ent = 0.f;
        for (int e = 0; e < NEXPG; e++) {
            float wge = eg[e] / sg;
            g_wg[b * NEXPG + e] = wge;
            ent -= wge * logf(wge + 1e-8f);
        }
        g_ent[b] = ent;
    }
}

__global__ void route_kernel() {
    int wid = threadIdx.x >> 5, lane = threadIdx.x & 31;
    if (wid >= NEXPA) return;
    int cnt = 0;
    for (int base = 0; base < BATCH; base += 32) {
        int b = base + lane;
        bool sel = (g_wa[b * NEXPA + wid] > 0.f);
        unsigned m = __ballot_sync(0xffffffffu, sel);
        if (sel) {
            int pos = cnt + __popc(m & ((1u << lane) - 1u));
            g_list[wid * BATCH + pos] = b;
            g_posOf[wid * BATCH + b]  = pos;
        }
        cnt += __popc(m);
    }
    if (lane == 0) g_cnt[wid] = cnt;
}

// ---------------- mma.sync GEMM (optionally routed) ----------------
// MODE 0: relu -> bf16 pair.  1: fp32.  2: tanh -> pair.  3: addend -> fp32+pair.  4: final.
template<int MODE>
__global__ __launch_bounds__(256, 1) void tgemm(
    const __nv_bfloat16* __restrict__ Ah, const __nv_bfloat16* __restrict__ Al, long long sAz,
    const __nv_bfloat16* __restrict__ Bh, const __nv_bfloat16* __restrict__ Bl, long long sBz,
    const float* __restrict__ bias, int sBias,
    float* __restrict__ Cf, long long sCfz,
    __nv_bfloat16* __restrict__ Ch, __nv_bfloat16* __restrict__ Cl, long long sCpz,
    const float* __restrict__ addend, const float* __restrict__ ex1, const float* __restrict__ ex2,
    const float* __restrict__ pt, const float* __restrict__ tscale,
    const int* __restrict__ rowsA, const int* __restrict__ cntArr,
    int K, int N)
{
    extern __shared__ char smem[];
    int z = blockIdx.z;
    int Mtot = cntArr ? cntArr[z] : BATCH;
    int bm = blockIdx.y * BMT;
    if (bm >= Mtot) return;
    int bn = blockIdx.x * BNT;
    int tid = threadIdx.x, lane = tid & 31, wid = tid >> 5;
    int wm = (wid & 3) * 32, wn = (wid >> 2) * 64;
    uint32_t sb = smem_u32(smem);
    const uint32_t oAh = 0, oAl = 2 * STG_B, oBh = 4 * STG_B, oBl = 6 * STG_B;

    const __nv_bfloat16* gAh = Ah + (size_t)z * sAz;
    const __nv_bfloat16* gAl = Al + (size_t)z * sAz;
    const __nv_bfloat16* gBh = Bh + (size_t)z * sBz;
    const __nv_bfloat16* gBl = Bl + (size_t)z * sBz;

    int r0 = tid >> 2, o0 = (tid & 3) * 8;
    int r1 = (tid + 256) >> 2, o1 = ((tid + 256) & 3) * 8;
    // A-row gather (clamped)
    int am0 = bm + r0 < Mtot ? bm + r0 : 0;
    int am1 = bm + r1 < Mtot ? bm + r1 : 0;
    if (rowsA) { am0 = rowsA[(size_t)z * BATCH + am0]; am1 = rowsA[(size_t)z * BATCH + am1]; }

    float cacc[2][8][4];
    #pragma unroll
    for (int i = 0; i < 2; i++)
        #pragma unroll
        for (int j = 0; j < 8; j++)
            #pragma unroll
            for (int q = 0; q < 4; q++) cacc[i][j][q] = 0.f;

    int nIter = K >> 5;
    auto load_stage = [&](int it) {
        int p = it & 1;
        size_t k0 = (size_t)it * BKT;
        CP_ASYNC16(sb + oAh + p * STG_B + (r0 * RS + o0) * 2, gAh + (size_t)am0 * K + k0 + o0);
        CP_ASYNC16(sb + oAh + p * STG_B + (r1 * RS + o1) * 2, gAh + (size_t)am1 * K + k0 + o1);
        CP_ASYNC16(sb + oAl + p * STG_B + (r0 * RS + o0) * 2, gAl + (size_t)am0 * K + k0 + o0);
        CP_ASYNC16(sb + oAl + p * STG_B + (r1 * RS + o1) * 2, gAl + (size_t)am1 * K + k0 + o1);
        CP_ASYNC16(sb + oBh + p * STG_B + (r0 * RS + o0) * 2, gBh + (size_t)(bn + r0) * K + k0 + o0);
        CP_ASYNC16(sb + oBh + p * STG_B + (r1 * RS + o1) * 2, gBh + (size_t)(bn + r1) * K + k0 + o1);
        CP_ASYNC16(sb + oBl + p * STG_B + (r0 * RS + o0) * 2, gBl + (size_t)(bn + r0) * K + k0 + o0);
        CP_ASYNC16(sb + oBl + p * STG_B + (r1 * RS + o1) * 2, gBl + (size_t)(bn + r1) * K + k0 + o1);
        CP_COMMIT();
    };

    load_stage(0);
    int arow = wm + (lane & 15);
    int acolb = (lane >> 4) * 16;
    int brow = wn + (lane & 7) + ((lane >> 4) << 3);
    int bcolb = ((lane >> 3) & 1) * 16;

    for (int it = 0; it < nIter; it++) {
        int p = it & 1;
        CP_WAIT0();
        __syncthreads();
        if (it + 1 < nIter) load_stage(it + 1);
        uint32_t aBh = sb + oAh + p * STG_B, aBl_ = sb + oAl + p * STG_B;
        uint32_t bBh = sb + oBh + p * STG_B, bBl_ = sb + oBl + p * STG_B;
        #pragma unroll
        for (int ks = 0; ks < 2; ks++) {
            uint32_t af[2][2][4], bf[2][8][2];
            #pragma unroll
            for (int mt = 0; mt < 2; mt++) {
                uint32_t off = ((arow + mt * 16) * RS) * 2 + ks * 32 + acolb;
                LDM_X4(af[0][mt][0], af[0][mt][1], af[0][mt][2], af[0][mt][3], aBh + off);
                LDM_X4(af[1][mt][0], af[1][mt][1], af[1][mt][2], af[1][mt][3], aBl_ + off);
            }
            #pragma unroll
            for (int np = 0; np < 4; np++) {
                uint32_t off = ((brow + np * 16) * RS) * 2 + ks * 32 + bcolb;
                uint32_t t0, t1, t2, t3;
                LDM_X4(t0, t1, t2, t3, bBh + off);
                bf[0][np * 2][0] = t0; bf[0][np * 2][1] = t1;
                bf[0][np * 2 + 1][0] = t2; bf[0][np * 2 + 1][1] = t3;
                LDM_X4(t0, t1, t2, t3, bBl_ + off);
                bf[1][np * 2][0] = t0; bf[1][np * 2][1] = t1;
                bf[1][np * 2 + 1][0] = t2; bf[1][np * 2 + 1][1] = t3;
            }
            #pragma unroll
            for (int mt = 0; mt < 2; mt++)
                #pragma unroll
                for (int nt = 0; nt < 8; nt++) {
                    MMA16816(cacc[mt][nt], af[0][mt], bf[0][nt]);
                    MMA16816(cacc[mt][nt], af[0][mt], bf[1][nt]);
                    MMA16816(cacc[mt][nt], af[1][mt], bf[0][nt]);
                }
        }
        __syncthreads();
    }

    int gid = lane >> 2, tig = lane & 3;
    const float* bz = bias + (size_t)z * sBias;
    float* Cfz = (MODE != 0 && MODE != 2) ? Cf + (size_t)z * sCfz : nullptr;
    __nv_bfloat16* Chz = (MODE == 0 || MODE == 2 || MODE == 3) ? Ch + (size_t)z * sCpz : nullptr;
    __nv_bfloat16* Clz = (MODE == 0 || MODE == 2 || MODE == 3) ? Cl + (size_t)z * sCpz : nullptr;
    #pragma unroll
    for (int mt = 0; mt < 2; mt++) {
        int m0 = bm + wm + mt * 16 + gid;
        float s0 = 0.f, s8 = 0.f;
        if (MODE == 4) {
            float ts = tscale[0];
            s0 = ts * sqrtf(pt[m0] + 1e-8f);
            s8 = ts * sqrtf(pt[m0 + 8] + 1e-8f);
        }
        #pragma unroll
        for (int nt = 0; nt < 8; nt++) {
            int n0 = bn + wn + nt * 8 + tig * 2;
            float b0v = bz[n0], b1v = bz[n0 + 1];
            #pragma unroll
            for (int rr = 0; rr < 2; rr++) {
                int m = m0 + rr * 8;
                if (m >= Mtot) continue;
                float v0 = cacc[mt][nt][rr * 2 + 0] + b0v;
                float v1 = cacc[mt][nt][rr * 2 + 1] + b1v;
                size_t idx = (size_t)m * N + n0;
                if (MODE == 0) { v0 = fmaxf(v0, 0.f); v1 = fmaxf(v1, 0.f); }
                else if (MODE == 2) { v0 = tanhf(v0); v1 = tanhf(v1); }
                else if (MODE == 3) {
                    float2 ad = *(const float2*)(addend + idx);
                    v0 += ad.x; v1 += ad.y;
                    *(float2*)(Cfz + idx) = make_float2(v0, v1);
                } else if (MODE == 4) {
                    float2 e1 = *(const float2*)(ex1 + idx);
                    float2 e2 = *(const float2*)(ex2 + idx);
                    float sc = rr ? s8 : s0;
                    *(float2*)(Cfz + idx) = make_float2(
                        0.5f * (e1.x + e2.x) + sc * tanhf(v0),
                        0.5f * (e1.y + e2.y) + sc * tanhf(v1));
                } else {
                    *(float2*)(Cfz + idx) = make_float2(v0, v1);
                }
                if (MODE == 0 || MODE == 2 || MODE == 3) {
                    __nv_bfloat16 h0, l0, h1, l1;
                    split_bf16(v0, h0, l0); split_bf16(v1, h1, l1);
                    *(__nv_bfloat162*)(Chz + idx) = __nv_bfloat162(h0, h1);
                    *(__nv_bfloat162*)(Clz + idx) = __nv_bfloat162(l0, l1);
                }
            }
        }
    }
}

// ---------------- combine + reductions ----------------
__global__ __launch_bounds__(256) void combine_kernel() {
    int b = blockIdx.x, tid = threadIdx.x;
    __shared__ float wA[NEXPA], wG[NEXPG];
    __shared__ int posA[NEXPA];
    if (tid < NEXPA) {
        wA[tid] = g_wa[b * NEXPA + tid];
        posA[tid] = (wA[tid] > 0.f) ? g_posOf[tid * BATCH + b] : 0;
    }
    if (tid < NEXPG) wG[tid] = g_wg[b * NEXPG + tid];
    __syncthreads();
    float ss = 0.f;
    for (int n = tid; n < OUT_DIM; n += 256) {
        float op = 0.f, om = 0.f;
        #pragma unroll
        for (int e = 0; e < NEXPA; e++)
            if (wA[e] > 0.f)
                op += wA[e] * g_o[((size_t)e * BATCH + posA[e]) * OUT_DIM + n];
        #pragma unroll
        for (int e = 0; e < NEXPG; e++)
            om += wG[e] * g_o[((size_t)(12 + e) * BATCH + b) * OUT_DIM + n];
        size_t i = (size_t)b * OUT_DIM + n;
        g_out_p[i] = op; g_out_m[i] = om;
        float r = op - om;
        g_rep[i] = r; ss += r * r;
    }
    float tot = block_reduce_sum(ss);
    if (tid == 0) g_pt[b] = tot;
}
__global__ __launch_bounds__(256) void sumsq_kernel() {
    int b = blockIdx.x;
    float ss = 0.f;
    for (int n = threadIdx.x; n < OUT_DIM; n += 256) {
        float r = g_mr[(size_t)b * OUT_DIM + n];
        ss += r * r;
    }
    float tot = block_reduce_sum(ss);
    if (threadIdx.x == 0) g_pt[b] = tot;
}
__global__ __launch_bounds__(256) void mean_kernel(const float* __restrict__ src, float* __restrict__ dst) {
    float s = 0.f;
    for (int i = threadIdx.x; i < BATCH; i += 256) s += src[i];
    float tot = block_reduce_sum(s);
    if (threadIdx.x == 0) dst[0] = tot * (1.f / (float)BATCH);
}
__global__ __launch_bounds__(256) void h1_kernel(const float* __restrict__ w1,
                                                 const float* __restrict__ b1, int step) {
    int idx = blockIdx.x * blockDim.x + threadIdx.x;
    if (idx >= BATCH * HID_DIM) return;
    int b = idx >> 11, j = idx & 2047;
    float t = g_pt[b];
    float d = (step == 0) ? 0.f : (t - g_tens[step]);
    float sv = (float)step * (1.f / 3.f);
    float v = tanhf(t * w1[j] + d * w1[HID_DIM + j] + sv * w1[2 * HID_DIM + j] + b1[j]);
    __nv_bfloat16 h, l; split_bf16(v, h, l);
    c_h1h[idx] = h; c_h1l[idx] = l;
}
__global__ __launch_bounds__(256) void aux_kernel(float* __restrict__ out, int out_size) {
    float s = 0.f;
    for (int i = threadIdx.x; i < BATCH; i += 256) s += g_ent[i];
    float tot = block_reduce_sum(s);
    if (threadIdx.x == 0) {
        float h = tot * (1.f / (float)BATCH);
        float el = (h - H_TARGET) * (h - H_TARGET);
        float conv = (fabsf(g_tens[1] - g_tens[0]) + fabsf(g_tens[2] - g_tens[1]) +
                      fabsf(g_tens[3] - g_tens[2])) * (1.f / 3.f);
        float aux = el + 0.001f * conv;
        for (int j = BATCH * OUT_DIM; j < out_size; j++) out[j] = aux;
    }
}

// ---------------- launcher ----------------
extern "C" void kernel_launch(void* const* d_in, const int* in_sizes, int n_in,
                              void* d_out, int out_size) {
    (void)in_sizes; (void)n_in;
    const float* x    = (const float*)d_in[0];
    const float* gaw  = (const float*)d_in[1];
    const float* gab  = (const float*)d_in[2];
    const float* wa1  = (const float*)d_in[3];
    const float* ba1  = (const float*)d_in[4];
    const float* wa2  = (const float*)d_in[5];
    const float* ba2  = (const float*)d_in[6];
    const float* ggw  = (const float*)d_in[7];
    const float* ggb  = (const float*)d_in[8];
    const float* wg1  = (const float*)d_in[9];
    const float* bg1  = (const float*)d_in[10];
    const float* wg2  = (const float*)d_in[11];
    const float* bg2  = (const float*)d_in[12];
    const float* smw1 = (const float*)d_in[13];
    const float* smb1 = (const float*)d_in[14];
    const float* smw2 = (const float*)d_in[15];
    const float* smb2 = (const float*)d_in[16];
    const float* siw  = (const float*)d_in[17];
    const float* sib  = (const float*)d_in[18];
    const float* ftw  = (const float*)d_in[19];
    const float* ftb  = (const float*)d_in[20];
    const float* tsc  = (const float*)d_in[21];
    float* out = (float*)d_out;

    cudaFuncSetAttribute(tgemm<0>, cudaFuncAttributeMaxDynamicSharedMemorySize, SMEM_TOT);
    cudaFuncSetAttribute(tgemm<1>, cudaFuncAttributeMaxDynamicSharedMemorySize, SMEM_TOT);
    cudaFuncSetAttribute(tgemm<2>, cudaFuncAttributeMaxDynamicSharedMemorySize, SMEM_TOT);
    cudaFuncSetAttribute(tgemm<3>, cudaFuncAttributeMaxDynamicSharedMemorySize, SMEM_TOT);
    cudaFuncSetAttribute(tgemm<4>, cudaFuncAttributeMaxDynamicSharedMemorySize, SMEM_TOT);

    __nv_bfloat16 *p_xh, *p_xl, *p_hh, *p_hl, *p_w1h, *p_w1l, *p_w2h, *p_w2l;
    __nv_bfloat16 *p_smh, *p_sml, *p_sih, *p_sil, *p_fth, *p_ftl;
    __nv_bfloat16 *p_h1h, *p_h1l, *p_ssh, *p_ssl, *p_mrh, *p_mrl;
    float *p_o, *p_op, *p_om, *p_rep, *p_mr, *p_pt, *p_tens;
    int *p_cnt, *p_list;
    cudaGetSymbolAddress((void**)&p_xh, c_xh);   cudaGetSymbolAddress((void**)&p_xl, c_xl);
    cudaGetSymbolAddress((void**)&p_hh, c_hh);   cudaGetSymbolAddress((void**)&p_hl, c_hl);
    cudaGetSymbolAddress((void**)&p_w1h, c_w1h); cudaGetSymbolAddress((void**)&p_w1l, c_w1l);
    cudaGetSymbolAddress((void**)&p_w2h, c_w2h); cudaGetSymbolAddress((void**)&p_w2l, c_w2l);
    cudaGetSymbolAddress((void**)&p_smh, c_smh); cudaGetSymbolAddress((void**)&p_sml, c_sml);
    cudaGetSymbolAddress((void**)&p_sih, c_sih); cudaGetSymbolAddress((void**)&p_sil, c_sil);
    cudaGetSymbolAddress((void**)&p_fth, c_fth); cudaGetSymbolAddress((void**)&p_ftl, c_ftl);
    cudaGetSymbolAddress((void**)&p_h1h, c_h1h); cudaGetSymbolAddress((void**)&p_h1l, c_h1l);
    cudaGetSymbolAddress((void**)&p_ssh, c_ssh); cudaGetSymbolAddress((void**)&p_ssl, c_ssl);
    cudaGetSymbolAddress((void**)&p_mrh, c_mrh); cudaGetSymbolAddress((void**)&p_mrl, c_mrl);
    cudaGetSymbolAddress((void**)&p_o, g_o);     cudaGetSymbolAddress((void**)&p_op, g_out_p);
    cudaGetSymbolAddress((void**)&p_om, g_out_m); cudaGetSymbolAddress((void**)&p_rep, g_rep);
    cudaGetSymbolAddress((void**)&p_mr, g_mr);   cudaGetSymbolAddress((void**)&p_pt, g_pt);
    cudaGetSymbolAddress((void**)&p_tens, g_tens);
    cudaGetSymbolAddress((void**)&p_cnt, g_cnt); cudaGetSymbolAddress((void**)&p_list, g_list);

    convert_w<<<dim3(HID_DIM/32, IN_DIM/32, 12), 256>>>(wa1, p_w1h, p_w1l, IN_DIM, HID_DIM);
    convert_w<<<dim3(HID_DIM/32, IN_DIM/32, 6), 256>>>(wg1, p_w1h + (size_t)12*HID_DIM*IN_DIM,
                                                       p_w1l + (size_t)12*HID_DIM*IN_DIM, IN_DIM, HID_DIM);
    convert_w<<<dim3(OUT_DIM/32, HID_DIM/32, 12), 256>>>(wa2, p_w2h, p_w2l, HID_DIM, OUT_DIM);
    convert_w<<<dim3(OUT_DIM/32, HID_DIM/32, 6), 256>>>(wg2, p_w2h + (size_t)12*OUT_DIM*HID_DIM,
                                                        p_w2l + (size_t)12*OUT_DIM*HID_DIM, HID_DIM, OUT_DIM);
    convert_w<<<dim3(OUT_DIM/32, HID_DIM/32, 1), 256>>>(smw2, p_smh, p_sml, HID_DIM, OUT_DIM);
    convert_w<<<dim3(OUT_DIM/32, OUT_DIM/32, 1), 256>>>(siw, p_sih, p_sil, OUT_DIM, OUT_DIM);
    convert_w<<<dim3(OUT_DIM/32, OUT_DIM/32, 1), 256>>>(ftw, p_fth, p_ftl, OUT_DIM, OUT_DIM);
    split_act<<<(BATCH*IN_DIM+255)/256, 256>>>(x, p_xh, p_xl, BATCH*IN_DIM);

    gate_kernel<<<BATCH, 256>>>(x, gaw, gab, ggw, ggb);
    route_kernel<<<1, NEXPA * 32>>>();

    dim3 gL1(HID_DIM/BNT, BATCH/BMT, 12), gL1g(HID_DIM/BNT, BATCH/BMT, 6);
    dim3 gL2(OUT_DIM/BNT, BATCH/BMT, 12), gL2g(OUT_DIM/BNT, BATCH/BMT, 6);
    dim3 g1(OUT_DIM/BNT, BATCH/BMT, 1);
    long long sW1 = (long long)HID_DIM*IN_DIM, sW2 = (long long)OUT_DIM*HID_DIM;
    long long sH = (long long)BATCH*HID_DIM, sO = (long long)BATCH*OUT_DIM;

    // EngineA routed: layer1 gathers x rows per expert -> compact hidden
    tgemm<0><<<gL1, 256, SMEM_TOT>>>(p_xh, p_xl, 0, p_w1h, p_w1l, sW1, ba1, HID_DIM,
        nullptr, 0, p_hh, p_hl, sH, nullptr, nullptr, nullptr, nullptr, nullptr,
        p_list, p_cnt, IN_DIM, HID_DIM);
    // EngineG dense layer1
    tgemm<0><<<gL1g, 256, SMEM_TOT>>>(p_xh, p_xl, 0, p_w1h + 12*sW1, p_w1l + 12*sW1, sW1, bg1, HID_DIM,
        nullptr, 0, p_hh + 12*sH, p_hl + 12*sH, sH, nullptr, nullptr, nullptr, nullptr, nullptr,
        nullptr, nullptr, IN_DIM, HID_DIM);
    // EngineA routed layer2 (compact rows in/out)
    tgemm<1><<<gL2, 256, SMEM_TOT>>>(p_hh, p_hl, sH, p_w2h, p_w2l, sW2, ba2, OUT_DIM,
        p_o, sO, nullptr, nullptr, 0, nullptr, nullptr, nullptr, nullptr, nullptr,
        nullptr, p_cnt, HID_DIM, OUT_DIM);
    // EngineG dense layer2
    tgemm<1><<<gL2g, 256, SMEM_TOT>>>(p_hh + 12*sH, p_hl + 12*sH, sH, p_w2h + 12*sW2, p_w2l + 12*sW2, sW2,
        bg2, OUT_DIM, p_o + 12*sO, sO, nullptr, nullptr, 0, nullptr, nullptr, nullptr, nullptr, nullptr,
        nullptr, nullptr, HID_DIM, OUT_DIM);

    combine_kernel<<<BATCH, 256>>>();
    mean_kernel<<<1, 256>>>(p_pt, p_tens);

    for (int s = 0; s < 3; s++) {
        h1_kernel<<<(BATCH*HID_DIM+255)/256, 256>>>(smw1, smb1, s);
        tgemm<2><<<g1, 256, SMEM_TOT>>>(p_h1h, p_h1l, 0, p_smh, p_sml, 0, smb2, 0,
            nullptr, 0, p_ssh, p_ssl, 0, nullptr, nullptr, nullptr, nullptr, nullptr,
            nullptr, nullptr, HID_DIM, OUT_DIM);
        tgemm<3><<<g1, 256, SMEM_TOT>>>(p_ssh, p_ssl, 0, p_sih, p_sil, 0, sib, 0,
            p_mr, 0, p_mrh, p_mrl, 0, p_rep, nullptr, nullptr, nullptr, nullptr,
            nullptr, nullptr, OUT_DIM, OUT_DIM);
        sumsq_kernel<<<BATCH, 256>>>();
        mean_kernel<<<1, 256>>>(p_pt, p_tens + s + 1);
    }

    tgemm<4><<<g1, 256, SMEM_TOT>>>(p_mrh, p_mrl, 0, p_fth, p_ftl, 0, ftb, 0,
        out, 0, nullptr, nullptr, 0, nullptr, p_op, p_om, p_pt, tsc,
        nullptr, nullptr, OUT_DIM, OUT_DIM);
    aux_kernel<<<1, 256>>>(out, out_size);
}

// round 6
// speedup vs baseline: 5.5195x; 1.1372x over previous
#include <cuda_runtime.h>
#include <cuda_bf16.h>
#include <cstdint>
#include <math.h>

#define BATCH   2048
#define IN_DIM  1024
#define HID_DIM 2048
#define OUT_DIM 1024
#define NEXPA   12
#define NEXPG   6
#define NEXP    18
#define H_TARGET 1.0114042647073518f

#define BMT 128
#define BNT 128
#define BKT 32
#define RS  40
#define STG_B (128 * RS * 2)
#define SMEM_TOT (8 * STG_B)

// ---------------- device scratch ----------------
__device__ __nv_bfloat16 c_xh[BATCH * IN_DIM],  c_xl[BATCH * IN_DIM];
__device__ __nv_bfloat16 c_hh[(size_t)NEXP * BATCH * HID_DIM];
__device__ __nv_bfloat16 c_hl[(size_t)NEXP * BATCH * HID_DIM];
__device__ float         g_o [(size_t)NEXP * BATCH * OUT_DIM];
__device__ __nv_bfloat16 c_w1h[(size_t)NEXP * HID_DIM * IN_DIM], c_w1l[(size_t)NEXP * HID_DIM * IN_DIM];
__device__ __nv_bfloat16 c_w2h[(size_t)NEXP * OUT_DIM * HID_DIM], c_w2l[(size_t)NEXP * OUT_DIM * HID_DIM];
__device__ __nv_bfloat16 c_smh[OUT_DIM * HID_DIM], c_sml[OUT_DIM * HID_DIM];
__device__ __nv_bfloat16 c_sih[OUT_DIM * OUT_DIM], c_sil[OUT_DIM * OUT_DIM];
__device__ __nv_bfloat16 c_fth[OUT_DIM * OUT_DIM], c_ftl[OUT_DIM * OUT_DIM];
__device__ __nv_bfloat16 c_h1h[BATCH * HID_DIM], c_h1l[BATCH * HID_DIM];
__device__ __nv_bfloat16 c_ssh[BATCH * OUT_DIM], c_ssl[BATCH * OUT_DIM];
__device__ __nv_bfloat16 c_mrh[BATCH * OUT_DIM], c_mrl[BATCH * OUT_DIM];
__device__ float g_out_p[BATCH * OUT_DIM], g_out_m[BATCH * OUT_DIM];
__device__ float g_rep[BATCH * OUT_DIM], g_mr[BATCH * OUT_DIM];
__device__ float g_wa[BATCH * NEXPA], g_wg[BATCH * NEXPG];
__device__ float g_ent[BATCH], g_pt[BATCH], g_tens[8];
__device__ int   g_cnt[NEXPA];
__device__ int   g_list[NEXPA * BATCH];
__device__ int   g_posOf[NEXPA * BATCH];

// ---------------- helpers ----------------
__device__ __forceinline__ float block_reduce_sum(float v) {
    __shared__ float s[32];
    int lane = threadIdx.x & 31, w = threadIdx.x >> 5;
    #pragma unroll
    for (int o = 16; o > 0; o >>= 1) v += __shfl_down_sync(0xffffffffu, v, o);
    if (lane == 0) s[w] = v;
    __syncthreads();
    v = (threadIdx.x < (blockDim.x >> 5)) ? s[threadIdx.x] : 0.f;
    if (w == 0)
        #pragma unroll
        for (int o = 16; o > 0; o >>= 1) v += __shfl_down_sync(0xffffffffu, v, o);
    return v;
}
__device__ __forceinline__ void split_bf16(float v, __nv_bfloat16& h, __nv_bfloat16& l) {
    h = __float2bfloat16(v);
    l = __float2bfloat16(v - __bfloat162float(h));
}
__device__ __forceinline__ uint32_t smem_u32(const void* p) {
    uint32_t a;
    asm("{ .reg .u64 t; cvta.to.shared.u64 t, %1; cvt.u32.u64 %0, t; }" : "=r"(a) : "l"(p));
    return a;
}
#define CP_ASYNC16(dst, src) \
    asm volatile("cp.async.ca.shared.global [%0], [%1], 16;" :: "r"(dst), "l"(src))
#define CP_COMMIT() asm volatile("cp.async.commit_group;")
#define CP_WAIT0()  asm volatile("cp.async.wait_group 0;")
#define LDM_X4(r0,r1,r2,r3,a) \
    asm volatile("ldmatrix.sync.aligned.m8n8.x4.shared.b16 {%0,%1,%2,%3}, [%4];" \
        : "=r"(r0), "=r"(r1), "=r"(r2), "=r"(r3) : "r"(a))
#define MMA16816(c, a, b) \
    asm volatile("mma.sync.aligned.m16n8k16.row.col.f32.bf16.bf16.f32 " \
        "{%0,%1,%2,%3}, {%4,%5,%6,%7}, {%8,%9}, {%0,%1,%2,%3};" \
        : "+f"((c)[0]), "+f"((c)[1]), "+f"((c)[2]), "+f"((c)[3]) \
        : "r"((a)[0]), "r"((a)[1]), "r"((a)[2]), "r"((a)[3]), "r"((b)[0]), "r"((b)[1]))

// ---------------- conversions ----------------
__global__ __launch_bounds__(256) void split_act(const float* __restrict__ src,
    __nv_bfloat16* __restrict__ h, __nv_bfloat16* __restrict__ l, int n) {
    int i = blockIdx.x * 256 + threadIdx.x;
    if (i < n) { __nv_bfloat16 hh, ll; split_bf16(src[i], hh, ll); h[i] = hh; l[i] = ll; }
}
__global__ __launch_bounds__(256) void convert_w(const float* __restrict__ W,
    __nv_bfloat16* __restrict__ Wh, __nv_bfloat16* __restrict__ Wl, int K, int N) {
    __shared__ float t[32][33];
    size_t zo = (size_t)blockIdx.z * K * N;
    int k0 = blockIdx.y * 32, n0 = blockIdx.x * 32;
    int tx = threadIdx.x & 31, ty = threadIdx.x >> 5;
    #pragma unroll
    for (int i = 0; i < 4; i++)
        t[ty + i * 8][tx] = W[zo + (size_t)(k0 + ty + i * 8) * N + n0 + tx];
    __syncthreads();
    #pragma unroll
    for (int i = 0; i < 4; i++) {
        int n = n0 + ty + i * 8;
        __nv_bfloat16 h, l; split_bf16(t[tx][ty + i * 8], h, l);
        Wh[zo + (size_t)n * K + k0 + tx] = h;
        Wl[zo + (size_t)n * K + k0 + tx] = l;
    }
}

// ---------------- gating + routing ----------------
__global__ __launch_bounds__(256) void gate_kernel(
    const float* __restrict__ x, const float* __restrict__ gaw, const float* __restrict__ gab,
    const float* __restrict__ ggw, const float* __restrict__ ggb) {
    int b = blockIdx.x, tid = threadIdx.x;
    float acc[18];
    #pragma unroll
    for (int e = 0; e < 18; e++) acc[e] = 0.f;
    const float* xr = x + (size_t)b * IN_DIM;
    for (int i = tid; i < IN_DIM; i += 256) {
        float xv = xr[i];
        #pragma unroll
        for (int e = 0; e < NEXPA; e++) acc[e] = fmaf(xv, gaw[i * NEXPA + e], acc[e]);
        #pragma unroll
        for (int e = 0; e < NEXPG; e++) acc[12 + e] = fmaf(xv, ggw[i * NEXPG + e], acc[12 + e]);
    }
    __shared__ float s[18][8];
    int lane = tid & 31, w = tid >> 5;
    #pragma unroll
    for (int e = 0; e < 18; e++) {
        float v = acc[e];
        #pragma unroll
        for (int o = 16; o > 0; o >>= 1) v += __shfl_down_sync(0xffffffffu, v, o);
        if (lane == 0) s[e][w] = v;
    }
    __syncthreads();
    if (tid == 0) {
        float lg[18];
        for (int e = 0; e < 18; e++) {
            float v = 0.f;
            for (int ww = 0; ww < 8; ww++) v += s[e][ww];
            lg[e] = v + (e < 12 ? gab[e] : ggb[e - 12]);
        }
        bool used[NEXPA] = {false};
        int idxs[4]; float vals[4];
        for (int k = 0; k < 4; k++) {
            int bi = -1; float bv = -INFINITY;
            for (int e = 0; e < NEXPA; e++)
                if (!used[e] && lg[e] > bv) { bv = lg[e]; bi = e; }
            used[bi] = true; idxs[k] = bi; vals[k] = bv;
        }
        float m = vals[0], sum = 0.f, wv[4];
        for (int k = 0; k < 4; k++) { wv[k] = expf(vals[k] - m); sum += wv[k]; }
        for (int e = 0; e < NEXPA; e++) g_wa[b * NEXPA + e] = 0.f;
        for (int k = 0; k < 4; k++) g_wa[b * NEXPA + idxs[k]] = wv[k] / sum;
        float mg = -INFINITY;
        for (int e = 0; e < NEXPG; e++) mg = fmaxf(mg, lg[12 + e]);
        float sg = 0.f, eg[NEXPG];
        for (int e = 0; e < NEXPG; e++) { eg[e] = expf(lg[12 + e] - mg); sg += eg[e]; }
        float ent = 0.f;
        for (int e = 0; e < NEXPG; e++) {
            float wge = eg[e] / sg;
            g_wg[b * NEXPG + e] = wge;
            ent -= wge * logf(wge + 1e-8f);
        }
        g_ent[b] = ent;
    }
}

__global__ void route_kernel() {
    int wid = threadIdx.x >> 5, lane = threadIdx.x & 31;
    if (wid >= NEXPA) return;
    int cnt = 0;
    for (int base = 0; base < BATCH; base += 32) {
        int b = base + lane;
        bool sel = (g_wa[b * NEXPA + wid] > 0.f);
        unsigned m = __ballot_sync(0xffffffffu, sel);
        if (sel) {
            int pos = cnt + __popc(m & ((1u << lane) - 1u));
            g_list[wid * BATCH + pos] = b;
            g_posOf[wid * BATCH + b]  = pos;
        }
        cnt += __popc(m);
    }
    if (lane == 0) g_cnt[wid] = cnt;
}

// ---------------- mma.sync GEMM ----------------
// MODE 0: relu->pair. 1: fp32. 2: tanh->pair. 3: addend->fp32+pair. 4: final.
template<int MODE>
__global__ __launch_bounds__(256, 2) void tgemm(
    const __nv_bfloat16* __restrict__ Ah, const __nv_bfloat16* __restrict__ Al, long long sAz,
    const __nv_bfloat16* __restrict__ Bh, const __nv_bfloat16* __restrict__ Bl, long long sBz,
    const float* __restrict__ bias, int sBias,
    float* __restrict__ Cf, long long sCfz,
    __nv_bfloat16* __restrict__ Ch, __nv_bfloat16* __restrict__ Cl, long long sCpz,
    const float* __restrict__ addend, const float* __restrict__ ex1, const float* __restrict__ ex2,
    const float* __restrict__ pt, const float* __restrict__ tscale,
    const int* __restrict__ rowsA, const int* __restrict__ cntArr,
    int K, int N)
{
    extern __shared__ char smem[];
    int z = blockIdx.z;
    int Mtot = cntArr ? cntArr[z] : BATCH;
    int bm = blockIdx.y * BMT;
    if (bm >= Mtot) return;
    int bn = blockIdx.x * BNT;
    int tid = threadIdx.x, lane = tid & 31, wid = tid >> 5;
    int wm = (wid & 3) * 32, wn = (wid >> 2) * 64;
    uint32_t sb = smem_u32(smem);
    const uint32_t oAh = 0, oAl = 2 * STG_B, oBh = 4 * STG_B, oBl = 6 * STG_B;

    const __nv_bfloat16* gAh = Ah + (size_t)z * sAz;
    const __nv_bfloat16* gAl = Al + (size_t)z * sAz;
    const __nv_bfloat16* gBh = Bh + (size_t)z * sBz;
    const __nv_bfloat16* gBl = Bl + (size_t)z * sBz;

    int r0 = tid >> 2, o0 = (tid & 3) * 8;
    int r1 = (tid + 256) >> 2, o1 = ((tid + 256) & 3) * 8;
    int am0 = bm + r0 < Mtot ? bm + r0 : 0;
    int am1 = bm + r1 < Mtot ? bm + r1 : 0;
    if (rowsA) { am0 = rowsA[(size_t)z * BATCH + am0]; am1 = rowsA[(size_t)z * BATCH + am1]; }

    float cacc[2][8][4];
    #pragma unroll
    for (int i = 0; i < 2; i++)
        #pragma unroll
        for (int j = 0; j < 8; j++)
            #pragma unroll
            for (int q = 0; q < 4; q++) cacc[i][j][q] = 0.f;

    int nIter = K >> 5;
    auto load_stage = [&](int it) {
        int p = it & 1;
        size_t k0 = (size_t)it * BKT;
        CP_ASYNC16(sb + oAh + p * STG_B + (r0 * RS + o0) * 2, gAh + (size_t)am0 * K + k0 + o0);
        CP_ASYNC16(sb + oAh + p * STG_B + (r1 * RS + o1) * 2, gAh + (size_t)am1 * K + k0 + o1);
        CP_ASYNC16(sb + oAl + p * STG_B + (r0 * RS + o0) * 2, gAl + (size_t)am0 * K + k0 + o0);
        CP_ASYNC16(sb + oAl + p * STG_B + (r1 * RS + o1) * 2, gAl + (size_t)am1 * K + k0 + o1);
        CP_ASYNC16(sb + oBh + p * STG_B + (r0 * RS + o0) * 2, gBh + (size_t)(bn + r0) * K + k0 + o0);
        CP_ASYNC16(sb + oBh + p * STG_B + (r1 * RS + o1) * 2, gBh + (size_t)(bn + r1) * K + k0 + o1);
        CP_ASYNC16(sb + oBl + p * STG_B + (r0 * RS + o0) * 2, gBl + (size_t)(bn + r0) * K + k0 + o0);
        CP_ASYNC16(sb + oBl + p * STG_B + (r1 * RS + o1) * 2, gBl + (size_t)(bn + r1) * K + k0 + o1);
        CP_COMMIT();
    };

    load_stage(0);
    int arow = wm + (lane & 15);
    int acolb = (lane >> 4) * 16;
    int brow = wn + (lane & 7) + ((lane >> 4) << 3);
    int bcolb = ((lane >> 3) & 1) * 16;

    for (int it = 0; it < nIter; it++) {
        int p = it & 1;
        CP_WAIT0();
        __syncthreads();
        if (it + 1 < nIter) load_stage(it + 1);
        uint32_t aBh = sb + oAh + p * STG_B, aBl_ = sb + oAl + p * STG_B;
        uint32_t bBh = sb + oBh + p * STG_B, bBl_ = sb + oBl + p * STG_B;
        #pragma unroll
        for (int ks = 0; ks < 2; ks++) {
            uint32_t af[2][2][4];
            #pragma unroll
            for (int mt = 0; mt < 2; mt++) {
                uint32_t off = ((arow + mt * 16) * RS) * 2 + ks * 32 + acolb;
                LDM_X4(af[0][mt][0], af[0][mt][1], af[0][mt][2], af[0][mt][3], aBh + off);
                LDM_X4(af[1][mt][0], af[1][mt][1], af[1][mt][2], af[1][mt][3], aBl_ + off);
            }
            // B fragments loaded per np pair: only 8 live regs
            #pragma unroll
            for (int np = 0; np < 4; np++) {
                uint32_t off = ((brow + np * 16) * RS) * 2 + ks * 32 + bcolb;
                uint32_t bh0[2], bh1[2], bl0[2], bl1[2];
                LDM_X4(bh0[0], bh0[1], bh1[0], bh1[1], bBh + off);
                LDM_X4(bl0[0], bl0[1], bl1[0], bl1[1], bBl_ + off);
                #pragma unroll
                for (int mt = 0; mt < 2; mt++) {
                    MMA16816(cacc[mt][np * 2],     af[0][mt], bh0);
                    MMA16816(cacc[mt][np * 2],     af[1][mt], bh0);
                    MMA16816(cacc[mt][np * 2],     af[0][mt], bl0);
                    MMA16816(cacc[mt][np * 2 + 1], af[0][mt], bh1);
                    MMA16816(cacc[mt][np * 2 + 1], af[1][mt], bh1);
                    MMA16816(cacc[mt][np * 2 + 1], af[0][mt], bl1);
                }
            }
        }
        __syncthreads();
    }

    int gid = lane >> 2, tig = lane & 3;
    const float* bz = bias + (size_t)z * sBias;
    float* Cfz = (MODE != 0 && MODE != 2) ? Cf + (size_t)z * sCfz : nullptr;
    __nv_bfloat16* Chz = (MODE == 0 || MODE == 2 || MODE == 3) ? Ch + (size_t)z * sCpz : nullptr;
    __nv_bfloat16* Clz = (MODE == 0 || MODE == 2 || MODE == 3) ? Cl + (size_t)z * sCpz : nullptr;
    #pragma unroll
    for (int mt = 0; mt < 2; mt++) {
        int m0 = bm + wm + mt * 16 + gid;
        float s0 = 0.f, s8 = 0.f;
        if (MODE == 4) {
            float ts = tscale[0];
            s0 = ts * sqrtf(pt[m0] + 1e-8f);
            s8 = ts * sqrtf(pt[m0 + 8] + 1e-8f);
        }
        #pragma unroll
        for (int nt = 0; nt < 8; nt++) {
            int n0 = bn + wn + nt * 8 + tig * 2;
            float b0v = bz[n0], b1v = bz[n0 + 1];
            #pragma unroll
            for (int rr = 0; rr < 2; rr++) {
                int m = m0 + rr * 8;
                if (m >= Mtot) continue;
                float v0 = cacc[mt][nt][rr * 2 + 0] + b0v;
                float v1 = cacc[mt][nt][rr * 2 + 1] + b1v;
                size_t idx = (size_t)m * N + n0;
                if (MODE == 0) { v0 = fmaxf(v0, 0.f); v1 = fmaxf(v1, 0.f); }
                else if (MODE == 2) { v0 = tanhf(v0); v1 = tanhf(v1); }
                else if (MODE == 3) {
                    float2 ad = *(const float2*)(addend + idx);
                    v0 += ad.x; v1 += ad.y;
                    *(float2*)(Cfz + idx) = make_float2(v0, v1);
                } else if (MODE == 4) {
                    float2 e1 = *(const float2*)(ex1 + idx);
                    float2 e2 = *(const float2*)(ex2 + idx);
                    float sc = rr ? s8 : s0;
                    *(float2*)(Cfz + idx) = make_float2(
                        0.5f * (e1.x + e2.x) + sc * tanhf(v0),
                        0.5f * (e1.y + e2.y) + sc * tanhf(v1));
                } else {
                    *(float2*)(Cfz + idx) = make_float2(v0, v1);
                }
                if (MODE == 0 || MODE == 2 || MODE == 3) {
                    __nv_bfloat16 h0, l0, h1, l1;
                    split_bf16(v0, h0, l0); split_bf16(v1, h1, l1);
                    *(__nv_bfloat162*)(Chz + idx) = __nv_bfloat162(h0, h1);
                    *(__nv_bfloat162*)(Clz + idx) = __nv_bfloat162(l0, l1);
                }
            }
        }
    }
}

// ---------------- combine + reductions ----------------
__global__ __launch_bounds__(256) void combine_kernel() {
    int b = blockIdx.x, tid = threadIdx.x;
    __shared__ float wA[NEXPA], wG[NEXPG];
    __shared__ int posA[NEXPA];
    if (tid < NEXPA) {
        wA[tid] = g_wa[b * NEXPA + tid];
        posA[tid] = (wA[tid] > 0.f) ? g_posOf[tid * BATCH + b] : 0;
    }
    if (tid < NEXPG) wG[tid] = g_wg[b * NEXPG + tid];
    __syncthreads();
    float ss = 0.f;
    for (int n = tid; n < OUT_DIM; n += 256) {
        float op = 0.f, om = 0.f;
        #pragma unroll
        for (int e = 0; e < NEXPA; e++)
            if (wA[e] > 0.f)
                op += wA[e] * g_o[((size_t)e * BATCH + posA[e]) * OUT_DIM + n];
        #pragma unroll
        for (int e = 0; e < NEXPG; e++)
            om += wG[e] * g_o[((size_t)(12 + e) * BATCH + b) * OUT_DIM + n];
        size_t i = (size_t)b * OUT_DIM + n;
        g_out_p[i] = op; g_out_m[i] = om;
        float r = op - om;
        g_rep[i] = r; ss += r * r;
    }
    float tot = block_reduce_sum(ss);
    if (tid == 0) g_pt[b] = tot;
}
__global__ __launch_bounds__(256) void sumsq_kernel() {
    int b = blockIdx.x;
    float ss = 0.f;
    for (int n = threadIdx.x; n < OUT_DIM; n += 256) {
        float r = g_mr[(size_t)b * OUT_DIM + n];
        ss += r * r;
    }
    float tot = block_reduce_sum(ss);
    if (threadIdx.x == 0) g_pt[b] = tot;
}
__global__ __launch_bounds__(256) void mean_kernel(const float* __restrict__ src, float* __restrict__ dst) {
    float s = 0.f;
    for (int i = threadIdx.x; i < BATCH; i += 256) s += src[i];
    float tot = block_reduce_sum(s);
    if (threadIdx.x == 0) dst[0] = tot * (1.f / (float)BATCH);
}
__global__ __launch_bounds__(256) void h1_kernel(const float* __restrict__ w1,
                                                 const float* __restrict__ b1, int step) {
    int idx = blockIdx.x * blockDim.x + threadIdx.x;
    if (idx >= BATCH * HID_DIM) return;
    int b = idx >> 11, j = idx & 2047;
    float t = g_pt[b];
    float d = (step == 0) ? 0.f : (t - g_tens[step]);
    float sv = (float)step * (1.f / 3.f);
    float v = tanhf(t * w1[j] + d * w1[HID_DIM + j] + sv * w1[2 * HID_DIM + j] + b1[j]);
    __nv_bfloat16 h, l; split_bf16(v, h, l);
    c_h1h[idx] = h; c_h1l[idx] = l;
}
__global__ __launch_bounds__(256) void aux_kernel(float* __restrict__ out, int out_size) {
    float s = 0.f;
    for (int i = threadIdx.x; i < BATCH; i += 256) s += g_ent[i];
    float tot = block_reduce_sum(s);
    if (threadIdx.x == 0) {
        float h = tot * (1.f / (float)BATCH);
        float el = (h - H_TARGET) * (h - H_TARGET);
        float conv = (fabsf(g_tens[1] - g_tens[0]) + fabsf(g_tens[2] - g_tens[1]) +
                      fabsf(g_tens[3] - g_tens[2])) * (1.f / 3.f);
        float aux = el + 0.001f * conv;
        for (int j = BATCH * OUT_DIM; j < out_size; j++) out[j] = aux;
    }
}

// ---------------- launcher ----------------
extern "C" void kernel_launch(void* const* d_in, const int* in_sizes, int n_in,
                              void* d_out, int out_size) {
    (void)in_sizes; (void)n_in;
    const float* x    = (const float*)d_in[0];
    const float* gaw  = (const float*)d_in[1];
    const float* gab  = (const float*)d_in[2];
    const float* wa1  = (const float*)d_in[3];
    const float* ba1  = (const float*)d_in[4];
    const float* wa2  = (const float*)d_in[5];
    const float* ba2  = (const float*)d_in[6];
    const float* ggw  = (const float*)d_in[7];
    const float* ggb  = (const float*)d_in[8];
    const float* wg1  = (const float*)d_in[9];
    const float* bg1  = (const float*)d_in[10];
    const float* wg2  = (const float*)d_in[11];
    const float* bg2  = (const float*)d_in[12];
    const float* smw1 = (const float*)d_in[13];
    const float* smb1 = (const float*)d_in[14];
    const float* smw2 = (const float*)d_in[15];
    const float* smb2 = (const float*)d_in[16];
    const float* siw  = (const float*)d_in[17];
    const float* sib  = (const float*)d_in[18];
    const float* ftw  = (const float*)d_in[19];
    const float* ftb  = (const float*)d_in[20];
    const float* tsc  = (const float*)d_in[21];
    float* out = (float*)d_out;

    cudaFuncSetAttribute(tgemm<0>, cudaFuncAttributeMaxDynamicSharedMemorySize, SMEM_TOT);
    cudaFuncSetAttribute(tgemm<1>, cudaFuncAttributeMaxDynamicSharedMemorySize, SMEM_TOT);
    cudaFuncSetAttribute(tgemm<2>, cudaFuncAttributeMaxDynamicSharedMemorySize, SMEM_TOT);
    cudaFuncSetAttribute(tgemm<3>, cudaFuncAttributeMaxDynamicSharedMemorySize, SMEM_TOT);
    cudaFuncSetAttribute(tgemm<4>, cudaFuncAttributeMaxDynamicSharedMemorySize, SMEM_TOT);

    __nv_bfloat16 *p_xh, *p_xl, *p_hh, *p_hl, *p_w1h, *p_w1l, *p_w2h, *p_w2l;
    __nv_bfloat16 *p_smh, *p_sml, *p_sih, *p_sil, *p_fth, *p_ftl;
    __nv_bfloat16 *p_h1h, *p_h1l, *p_ssh, *p_ssl, *p_mrh, *p_mrl;
    float *p_o, *p_op, *p_om, *p_rep, *p_mr, *p_pt, *p_tens;
    int *p_cnt, *p_list;
    cudaGetSymbolAddress((void**)&p_xh, c_xh);   cudaGetSymbolAddress((void**)&p_xl, c_xl);
    cudaGetSymbolAddress((void**)&p_hh, c_hh);   cudaGetSymbolAddress((void**)&p_hl, c_hl);
    cudaGetSymbolAddress((void**)&p_w1h, c_w1h); cudaGetSymbolAddress((void**)&p_w1l, c_w1l);
    cudaGetSymbolAddress((void**)&p_w2h, c_w2h); cudaGetSymbolAddress((void**)&p_w2l, c_w2l);
    cudaGetSymbolAddress((void**)&p_smh, c_smh); cudaGetSymbolAddress((void**)&p_sml, c_sml);
    cudaGetSymbolAddress((void**)&p_sih, c_sih); cudaGetSymbolAddress((void**)&p_sil, c_sil);
    cudaGetSymbolAddress((void**)&p_fth, c_fth); cudaGetSymbolAddress((void**)&p_ftl, c_ftl);
    cudaGetSymbolAddress((void**)&p_h1h, c_h1h); cudaGetSymbolAddress((void**)&p_h1l, c_h1l);
    cudaGetSymbolAddress((void**)&p_ssh, c_ssh); cudaGetSymbolAddress((void**)&p_ssl, c_ssl);
    cudaGetSymbolAddress((void**)&p_mrh, c_mrh); cudaGetSymbolAddress((void**)&p_mrl, c_mrl);
    cudaGetSymbolAddress((void**)&p_o, g_o);     cudaGetSymbolAddress((void**)&p_op, g_out_p);
    cudaGetSymbolAddress((void**)&p_om, g_out_m); cudaGetSymbolAddress((void**)&p_rep, g_rep);
    cudaGetSymbolAddress((void**)&p_mr, g_mr);   cudaGetSymbolAddress((void**)&p_pt, g_pt);
    cudaGetSymbolAddress((void**)&p_tens, g_tens);
    cudaGetSymbolAddress((void**)&p_cnt, g_cnt); cudaGetSymbolAddress((void**)&p_list, g_list);

    convert_w<<<dim3(HID_DIM/32, IN_DIM/32, 12), 256>>>(wa1, p_w1h, p_w1l, IN_DIM, HID_DIM);
    convert_w<<<dim3(HID_DIM/32, IN_DIM/32, 6), 256>>>(wg1, p_w1h + (size_t)12*HID_DIM*IN_DIM,
                                                       p_w1l + (size_t)12*HID_DIM*IN_DIM, IN_DIM, HID_DIM);
    convert_w<<<dim3(OUT_DIM/32, HID_DIM/32, 12), 256>>>(wa2, p_w2h, p_w2l, HID_DIM, OUT_DIM);
    convert_w<<<dim3(OUT_DIM/32, HID_DIM/32, 6), 256>>>(wg2, p_w2h + (size_t)12*OUT_DIM*HID_DIM,
                                                        p_w2l + (size_t)12*OUT_DIM*HID_DIM, HID_DIM, OUT_DIM);
    convert_w<<<dim3(OUT_DIM/32, HID_DIM/32, 1), 256>>>(smw2, p_smh, p_sml, HID_DIM, OUT_DIM);
    convert_w<<<dim3(OUT_DIM/32, OUT_DIM/32, 1), 256>>>(siw, p_sih, p_sil, OUT_DIM, OUT_DIM);
    convert_w<<<dim3(OUT_DIM/32, OUT_DIM/32, 1), 256>>>(ftw, p_fth, p_ftl, OUT_DIM, OUT_DIM);
    split_act<<<(BATCH*IN_DIM+255)/256, 256>>>(x, p_xh, p_xl, BATCH*IN_DIM);

    gate_kernel<<<BATCH, 256>>>(x, gaw, gab, ggw, ggb);
    route_kernel<<<1, NEXPA * 32>>>();

    dim3 gL1(HID_DIM/BNT, BATCH/BMT, 12), gL1g(HID_DIM/BNT, BATCH/BMT, 6);
    dim3 gL2(OUT_DIM/BNT, BATCH/BMT, 12), gL2g(OUT_DIM/BNT, BATCH/BMT, 6);
    dim3 g1(OUT_DIM/BNT, BATCH/BMT, 1);
    long long sW1 = (long long)HID_DIM*IN_DIM, sW2 = (long long)OUT_DIM*HID_DIM;
    long long sH = (long long)BATCH*HID_DIM, sO = (long long)BATCH*OUT_DIM;

    tgemm<0><<<gL1, 256, SMEM_TOT>>>(p_xh, p_xl, 0, p_w1h, p_w1l, sW1, ba1, HID_DIM,
        nullptr, 0, p_hh, p_hl, sH, nullptr, nullptr, nullptr, nullptr, nullptr,
        p_list, p_cnt, IN_DIM, HID_DIM);
    tgemm<0><<<gL1g, 256, SMEM_TOT>>>(p_xh, p_xl, 0, p_w1h + 12*sW1, p_w1l + 12*sW1, sW1, bg1, HID_DIM,
        nullptr, 0, p_hh + 12*sH, p_hl + 12*sH, sH, nullptr, nullptr, nullptr, nullptr, nullptr,
        nullptr, nullptr, IN_DIM, HID_DIM);
    tgemm<1><<<gL2, 256, SMEM_TOT>>>(p_hh, p_hl, sH, p_w2h, p_w2l, sW2, ba2, OUT_DIM,
        p_o, sO, nullptr, nullptr, 0, nullptr, nullptr, nullptr, nullptr, nullptr,
        nullptr, p_cnt, HID_DIM, OUT_DIM);
    tgemm<1><<<gL2g, 256, SMEM_TOT>>>(p_hh + 12*sH, p_hl + 12*sH, sH, p_w2h + 12*sW2, p_w2l + 12*sW2, sW2,
        bg2, OUT_DIM, p_o + 12*sO, sO, nullptr, nullptr, 0, nullptr, nullptr, nullptr, nullptr, nullptr,
        nullptr, nullptr, HID_DIM, OUT_DIM);

    combine_kernel<<<BATCH, 256>>>();
    mean_kernel<<<1, 256>>>(p_pt, p_tens);

    for (int s = 0; s < 3; s++) {
        h1_kernel<<<(BATCH*HID_DIM+255)/256, 256>>>(smw1, smb1, s);
        tgemm<2><<<g1, 256, SMEM_TOT>>>(p_h1h, p_h1l, 0, p_smh, p_sml, 0, smb2, 0,
            nullptr, 0, p_ssh, p_ssl, 0, nullptr, nullptr, nullptr, nullptr, nullptr,
            nullptr, nullptr, HID_DIM, OUT_DIM);
        tgemm<3><<<g1, 256, SMEM_TOT>>>(p_ssh, p_ssl, 0, p_sih, p_sil, 0, sib, 0,
            p_mr, 0, p_mrh, p_mrl, 0, p_rep, nullptr, nullptr, nullptr, nullptr,
            nullptr, nullptr, OUT_DIM, OUT_DIM);
        sumsq_kernel<<<BATCH, 256>>>();
        mean_kernel<<<1, 256>>>(p_pt, p_tens + s + 1);
    }

    tgemm<4><<<g1, 256, SMEM_TOT>>>(p_mrh, p_mrl, 0, p_fth, p_ftl, 0, ftb, 0,
        out, 0, nullptr, nullptr, 0, nullptr, p_op, p_om, p_pt, tsc,
        nullptr, nullptr, OUT_DIM, OUT_DIM);
    aux_kernel<<<1, 256>>>(out, out_size);
}